// round 11
// baseline (speedup 1.0000x reference)
#include <cuda_runtime.h>
#include <cuda_fp16.h>
#include <cstdint>
#include <cstddef>

constexpr int BATCH = 4, SEQ = 2048, DI = 4096, DO = 4096, RANK = 16;
constexpr int MTOT = BATCH * SEQ;          // 8192
constexpr float LORA_SCALE = 2.0f;         // ALPHA / RANK

constexpr int TM = 128, TN = 256, KC = 64; // K-chunk = 64 fp16 = 128B rows
constexpr int STAGES = 4;
constexpr int NCHUNK = DI / KC;            // 64 real chunks; chunk 64 = LoRA chunk
constexpr int A_BYTES = TM * 128;          // 16 KB
constexpr int B_BYTES = TN * 128;          // 32 KB
constexpr int STAGE_BYTES = A_BYTES + B_BYTES;           // 48 KB
constexpr int SMEM_BYTES = 1024 + STAGES * STAGE_BYTES;  // 197632

// Row swizzle over 16B chunk index (3 bits), conflict-free for v4 frag loads.
#define SWZ(r) (((((r) & 1) << 2) | (((r) >> 1) & 3)))

// ---------------- scratch (__device__ globals: allocation-free) -------------
// fp16 operands, permuted per 64-k group:
// pos(k) = s*32 + g*8 + G*4 + hi8*2 + e, where s=k>>5, kk=k&31, G=(kk>>4)&1,
// r=kk&15, hi8=r>>3, g=(r&7)>>1, e=k&1.
__device__ __align__(128) __half g_xp[(size_t)MTOT * DI];
__device__ __align__(128) __half g_wp[(size_t)DO * DI];
__device__ __align__(128) float  g_downw[BATCH * RANK * DI];      // fp32, scale folded
__device__ __align__(128) __half g_upp[(size_t)BATCH * DO * 64];  // K padded 64, perm
__device__ __align__(128) __half g_lrp[(size_t)MTOT * 64];        // K padded 64, perm

#define DEVFN __device__ __forceinline__

DEVFN uint32_t s2u(const void* p) {
    uint32_t a;
    asm("{ .reg .u64 t; cvta.to.shared.u64 t, %1; cvt.u32.u64 %0, t; }" : "=r"(a) : "l"(p));
    return a;
}
DEVFN void cp_async16(uint32_t dst, const void* src) {
    unsigned long long g = (unsigned long long)__cvta_generic_to_global((void*)src);
    asm volatile("cp.async.cg.shared.global [%0], [%1], 16;" :: "r"(dst), "l"(g));
}
#define CP_COMMIT() asm volatile("cp.async.commit_group;" ::: "memory")

DEVFN uint4 lds_v4u(uint32_t addr) {
    uint4 v;
    asm volatile("ld.shared.v4.b32 {%0,%1,%2,%3}, [%4];"
                 : "=r"(v.x), "=r"(v.y), "=r"(v.z), "=r"(v.w) : "r"(addr));
    return v;
}

// fp32-accumulate HMMA
DEVFN void mma16(float* d, uint32_t a0, uint32_t a1, uint32_t a2, uint32_t a3,
                 uint32_t b0, uint32_t b1) {
    asm volatile("mma.sync.aligned.m16n8k16.row.col.f32.f16.f16.f32 "
                 "{%0,%1,%2,%3}, {%4,%5,%6,%7}, {%8,%9}, {%0,%1,%2,%3};"
                 : "+f"(d[0]), "+f"(d[1]), "+f"(d[2]), "+f"(d[3])
                 : "r"(a0), "r"(a1), "r"(a2), "r"(a3), "r"(b0), "r"(b1));
}

DEVFN uint32_t h2u(__half2 h) { return *reinterpret_cast<uint32_t*>(&h); }

// ---------------------- W convert kernel (streaming) ------------------------
// one (s,G) half-supergroup (16 consecutive k) per thread; low regs, high occ
__global__ __launch_bounds__(256) void wconv_kernel(const float* __restrict__ W) {
    const size_t tid = (size_t)blockIdx.x * 256 + threadIdx.x;  // 1,048,576 threads
    const size_t grp = tid >> 2;                                // 64-k group index
    const int off = (int)(tid & 3) * 16;                        // 0,16,32,48
    const int sb = ((off >> 5) & 1) * 32 + ((off >> 4) & 1) * 4;
    const float* wp = W + grp * 64 + off;
    float v[16];
    #pragma unroll
    for (int q = 0; q < 4; q++) {
        float4 f = reinterpret_cast<const float4*>(wp)[q];
        v[4 * q] = f.x; v[4 * q + 1] = f.y; v[4 * q + 2] = f.z; v[4 * q + 3] = f.w;
    }
    __half* op = g_wp + grp * 64 + sb;
    #pragma unroll
    for (int g4 = 0; g4 < 4; g4++) {
        uint2 u;
        u.x = h2u(__floats2half2_rn(v[2 * g4], v[2 * g4 + 1]));
        u.y = h2u(__floats2half2_rn(v[8 + 2 * g4], v[9 + 2 * g4]));
        *reinterpret_cast<uint2*>(op + g4 * 8) = u;
    }
}

// ------------------------- small factors prep kernel ------------------------
// blocks [0,64): down factors; [64,128): up factors
__global__ __launch_bounds__(256) void prep_small_kernel(
    const float* __restrict__ da, const float* __restrict__ ua,
    const float* __restrict__ hd, const float* __restrict__ hu)
{
    __shared__ float hs[1024];
    const int bid = blockIdx.x, t = threadIdx.x;
    if (bid < 64) {
        // down[b][r][i] = scale * sum_a da[i,a] * hd[b,a,r]
        const int b = bid >> 4;
        const int i = (bid & 15) * 256 + t;
        for (int j = t; j < 1024; j += 256) hs[j] = hd[b * 1024 + j];  // hs[a*16+r]
        __syncthreads();
        float acc[16];
        #pragma unroll
        for (int r = 0; r < 16; r++) acc[r] = 0.f;
        const float4* dap = reinterpret_cast<const float4*>(da + (size_t)i * 64);
        #pragma unroll 4
        for (int aq = 0; aq < 16; aq++) {
            float4 v = dap[aq];
            #pragma unroll
            for (int r = 0; r < 16; r++)
                acc[r] += v.x * hs[(aq * 4 + 0) * 16 + r] + v.y * hs[(aq * 4 + 1) * 16 + r]
                        + v.z * hs[(aq * 4 + 2) * 16 + r] + v.w * hs[(aq * 4 + 3) * 16 + r];
        }
        #pragma unroll
        for (int r = 0; r < 16; r++)
            g_downw[((size_t)b * RANK + r) * DI + i] = LORA_SCALE * acc[r];
    } else {
        // up[b][o][c] = sum_a ua[a,o] * hu[b,c,a]; store fp16 permuted+padded
        const int bb2 = bid - 64;
        const int b = bb2 >> 4;
        const int o = (bb2 & 15) * 256 + t;
        for (int j = t; j < 1024; j += 256) hs[j] = hu[b * 1024 + j];  // hs[c*64+a]
        __syncthreads();
        float acc[16];
        #pragma unroll
        for (int c = 0; c < 16; c++) acc[c] = 0.f;
        #pragma unroll 4
        for (int a = 0; a < 64; a++) {
            float uv = ua[(size_t)a * DO + o];
            #pragma unroll
            for (int c = 0; c < 16; c++) acc[c] += uv * hs[c * 64 + a];
        }
        __half* op = g_upp + ((size_t)b * DO + o) * 64;
        #pragma unroll
        for (int q = 0; q < 4; q++) {
            uint2 v;
            v.x = h2u(__floats2half2_rn(acc[2 * q], acc[2 * q + 1]));
            v.y = h2u(__floats2half2_rn(acc[2 * q + 8], acc[2 * q + 9]));
            *reinterpret_cast<uint2*>(op + q * 8) = v;
            *reinterpret_cast<uint2*>(op + q * 8 + 4) = make_uint2(0, 0);
        }
        #pragma unroll
        for (int q = 0; q < 4; q++)
            *reinterpret_cast<uint4*>(op + 32 + q * 8) = make_uint4(0, 0, 0, 0);
    }
}

// smem swizzle for down_s: XOR 16B-chunk index with (chunk>>3)&7
DEVFN int dswz(int kk) {
    int c = kk >> 2;
    return ((c ^ ((c >> 3) & 7)) << 2) | (kk & 3);
}

// Fused: x -> fp16+perm copy AND low_rank = x @ down^T (scale folded in down).
// 32 rows per block, 8 warps x 4 rows (halves down_s staging vs 16-row).
__global__ __launch_bounds__(256) void lowrank_kernel(const float* __restrict__ x) {
    __shared__ float down_s[16 * 512];
    const int m0 = blockIdx.x * 32;
    const int bb = m0 / SEQ;
    const int t = threadIdx.x, w = t >> 5, l = t & 31;
    const int rowbase = m0 + w * 4;
    const float* dwb = g_downw + (size_t)bb * RANK * DI;

    const int ks = l * 16;
    const int o0 = dswz(ks), o1 = dswz(ks + 4), o2 = dswz(ks + 8), o3 = dswz(ks + 12);

    float acc[4][16];
    #pragma unroll
    for (int j = 0; j < 4; j++)
        #pragma unroll
        for (int r = 0; r < 16; r++) acc[j][r] = 0.f;

    for (int k0 = 0; k0 < DI; k0 += 512) {
        __syncthreads();
        for (int j = t; j < 16 * 512; j += 256) {
            int r = j >> 9, kk = j & 511;
            down_s[r * 512 + dswz(kk)] = dwb[r * DI + k0 + kk];
        }
        __syncthreads();
        const int gk = k0 + ks;
        const int grp = gk & ~63, off = gk & 63;
        const int sb = ((off >> 5) & 1) * 32 + ((off >> 4) & 1) * 4;
        #pragma unroll
        for (int j = 0; j < 4; j++) {
            const float* xr = x + (size_t)(rowbase + j) * DI + gk;
            float v[16];
            #pragma unroll
            for (int q = 0; q < 4; q++) {
                float4 f = reinterpret_cast<const float4*>(xr)[q];
                v[4 * q] = f.x; v[4 * q + 1] = f.y; v[4 * q + 2] = f.z; v[4 * q + 3] = f.w;
            }
            __half* op = g_xp + (size_t)(rowbase + j) * DI + grp + sb;
            #pragma unroll
            for (int g4 = 0; g4 < 4; g4++) {
                uint2 u;
                u.x = h2u(__floats2half2_rn(v[2 * g4], v[2 * g4 + 1]));
                u.y = h2u(__floats2half2_rn(v[8 + 2 * g4], v[9 + 2 * g4]));
                *reinterpret_cast<uint2*>(op + g4 * 8) = u;
            }
            #pragma unroll
            for (int r = 0; r < 16; r++) {
                const float* dr = down_s + r * 512;
                float4 d0 = *reinterpret_cast<const float4*>(dr + o0);
                float4 d1 = *reinterpret_cast<const float4*>(dr + o1);
                float4 d2 = *reinterpret_cast<const float4*>(dr + o2);
                float4 d3 = *reinterpret_cast<const float4*>(dr + o3);
                acc[j][r] += v[0] * d0.x + v[1] * d0.y + v[2] * d0.z + v[3] * d0.w
                           + v[4] * d1.x + v[5] * d1.y + v[6] * d1.z + v[7] * d1.w
                           + v[8] * d2.x + v[9] * d2.y + v[10] * d2.z + v[11] * d2.w
                           + v[12] * d3.x + v[13] * d3.y + v[14] * d3.z + v[15] * d3.w;
            }
        }
    }
    #pragma unroll
    for (int j = 0; j < 4; j++) {
        #pragma unroll
        for (int r = 0; r < 16; r++) {
            float v = acc[j][r];
            v += __shfl_xor_sync(~0u, v, 16);
            v += __shfl_xor_sync(~0u, v, 8);
            v += __shfl_xor_sync(~0u, v, 4);
            v += __shfl_xor_sync(~0u, v, 2);
            v += __shfl_xor_sync(~0u, v, 1);
            acc[j][r] = v;
        }
        if (l == 0) {
            __half* op = g_lrp + (size_t)(rowbase + j) * 64;
            #pragma unroll
            for (int q = 0; q < 4; q++) {
                uint2 u;
                u.x = h2u(__floats2half2_rn(acc[j][2 * q], acc[j][2 * q + 1]));
                u.y = h2u(__floats2half2_rn(acc[j][2 * q + 8], acc[j][2 * q + 9]));
                *reinterpret_cast<uint2*>(op + q * 8) = u;
                *reinterpret_cast<uint2*>(op + q * 8 + 4) = make_uint2(0, 0);
            }
            #pragma unroll
            for (int q = 0; q < 4; q++)
                *reinterpret_cast<uint4*>(op + 32 + q * 8) = make_uint4(0, 0, 0, 0);
        }
    }
}

// ------------------------------- main GEMM ----------------------------------
// 256 threads, 8 warps (2x4), warp tile 64x64, fp16 m16n8k16, 4 stages.
DEVFN void load_stage(int chunk, uint32_t sA, int m0, int n0, int bb) {
    const uint32_t sB = sA + A_BYTES;
    const int t = threadIdx.x;
    const __half *ap, *bp;
    size_t str;
    if (chunk < NCHUNK) {
        ap = g_xp + (size_t)m0 * DI + chunk * KC;
        bp = g_wp + (size_t)n0 * DI + chunk * KC;
        str = DI;
    } else {
        ap = g_lrp + (size_t)m0 * 64;
        bp = g_upp + ((size_t)bb * DO + n0) * 64;
        str = 64;
    }
    #pragma unroll
    for (int q = 0; q < 4; q++) {                       // A: 1024 chunks16
        int idx = t + q * 256, row = idx >> 3, ch = idx & 7;
        cp_async16(sA + row * 128 + (uint32_t)((ch ^ SWZ(row)) << 4),
                   ap + (size_t)row * str + ch * 8);
    }
    #pragma unroll
    for (int q = 0; q < 8; q++) {                       // B: 2048 chunks16
        int idx = t + q * 256, row = idx >> 3, ch = idx & 7;
        cp_async16(sB + row * 128 + (uint32_t)((ch ^ SWZ(row)) << 4),
                   bp + (size_t)row * str + ch * 8);
    }
}

__global__ void __launch_bounds__(256, 1)
gemm_kernel(const float* __restrict__ bias, float* __restrict__ out) {
    extern __shared__ char smem_raw[];
    float* bias_s = reinterpret_cast<float*>(smem_raw);   // 256 floats
    const uint32_t stage_u = s2u(smem_raw + 1024);

    const int t = threadIdx.x;
    const int wid = t >> 5, lane = t & 31;
    const int gID = lane >> 2, g = lane & 3;
    const int warpM = wid >> 2, warpN = wid & 3;          // 2 x 4 warps, 64x64 tiles

    const int n0 = blockIdx.x * TN;
    const int m0 = blockIdx.y * TM;
    const int bb = m0 / SEQ;

    bias_s[t] = bias[n0 + t];

    float acc[4][8][4];
    #pragma unroll
    for (int mf = 0; mf < 4; mf++)
        #pragma unroll
        for (int nf = 0; nf < 8; nf++)
            #pragma unroll
            for (int k = 0; k < 4; k++) acc[mf][nf][k] = 0.f;

    load_stage(0, stage_u + 0 * STAGE_BYTES, m0, n0, bb); CP_COMMIT();
    load_stage(1, stage_u + 1 * STAGE_BYTES, m0, n0, bb); CP_COMMIT();
    load_stage(2, stage_u + 2 * STAGE_BYTES, m0, n0, bb); CP_COMMIT();

    for (int c = 0; c <= NCHUNK; c++) {
        int rem = NCHUNK - c;
        if (rem >= 2)      asm volatile("cp.async.wait_group 2;" ::: "memory");
        else if (rem == 1) asm volatile("cp.async.wait_group 1;" ::: "memory");
        else               asm volatile("cp.async.wait_group 0;" ::: "memory");
        __syncthreads();
        if (c + 3 <= NCHUNK) {
            load_stage(c + 3, stage_u + ((c + 3) & 3) * STAGE_BYTES, m0, n0, bb);
            CP_COMMIT();
        }
        const uint32_t sAc = stage_u + (c & 3) * STAGE_BYTES;
        const uint32_t sBc = sAc + A_BYTES;
        #pragma unroll
        for (int s = 0; s < 2; s++) {
            const uint32_t cw = (uint32_t)(4 * s + g);
            uint4 A0[4], A1[4];
            #pragma unroll
            for (int mf = 0; mf < 4; mf++) {
                int row0 = warpM * 64 + mf * 16 + gID;
                int row1 = row0 + 8;
                A0[mf] = lds_v4u(sAc + row0 * 128 + ((cw ^ SWZ(row0)) << 4));
                A1[mf] = lds_v4u(sAc + row1 * 128 + ((cw ^ SWZ(row1)) << 4));
            }
            #pragma unroll
            for (int half = 0; half < 2; half++) {
                uint4 Bf[4];
                #pragma unroll
                for (int j = 0; j < 4; j++) {
                    int row = warpN * 64 + (half * 4 + j) * 8 + gID;
                    Bf[j] = lds_v4u(sBc + row * 128 + ((cw ^ SWZ(row)) << 4));
                }
                #pragma unroll
                for (int mf = 0; mf < 4; mf++)
                    #pragma unroll
                    for (int j = 0; j < 4; j++) {
                        float* d = acc[mf][half * 4 + j];
                        mma16(d, A0[mf].x, A1[mf].x, A0[mf].y, A1[mf].y,
                              Bf[j].x, Bf[j].y);
                        mma16(d, A0[mf].z, A1[mf].z, A0[mf].w, A1[mf].w,
                              Bf[j].z, Bf[j].w);
                    }
            }
        }
    }

    // epilogue: c0:(gID, 2g) c1:(gID, 2g+1) c2:(gID+8, 2g) c3:(gID+8, 2g+1)
    #pragma unroll
    for (int mf = 0; mf < 4; mf++) {
        const int r0 = m0 + warpM * 64 + mf * 16 + gID;
        #pragma unroll
        for (int nf = 0; nf < 8; nf++) {
            const int col = warpN * 64 + nf * 8 + 2 * g;
            const float b0 = bias_s[col], b1 = bias_s[col + 1];
            float2 v0, v1;
            v0.x = acc[mf][nf][0] + b0; v0.y = acc[mf][nf][1] + b1;
            v1.x = acc[mf][nf][2] + b0; v1.y = acc[mf][nf][3] + b1;
            *reinterpret_cast<float2*>(out + (size_t)r0 * DO + n0 + col) = v0;
            *reinterpret_cast<float2*>(out + (size_t)(r0 + 8) * DO + n0 + col) = v1;
        }
    }
}

// ------------------------------- launch -------------------------------------
extern "C" void kernel_launch(void* const* d_in, const int* /*in_sizes*/, int /*n_in*/,
                              void* d_out, int /*out_size*/) {
    const float* x  = (const float*)d_in[0];
    const float* W  = (const float*)d_in[1];
    const float* b  = (const float*)d_in[2];
    const float* da = (const float*)d_in[3];
    const float* ua = (const float*)d_in[4];
    const float* hd = (const float*)d_in[5];
    const float* hu = (const float*)d_in[6];
    float* out = (float*)d_out;

    cudaFuncSetAttribute(gemm_kernel, cudaFuncAttributeMaxDynamicSharedMemorySize, SMEM_BYTES);

    prep_small_kernel<<<128, 256>>>(da, ua, hd, hu);
    wconv_kernel<<<DO * DI / 16 / 256, 256>>>(W);
    lowrank_kernel<<<MTOT / 32, 256>>>(x);
    gemm_kernel<<<dim3(DO / TN, MTOT / TM), 256, SMEM_BYTES>>>(b, out);
}

// round 12
// speedup vs baseline: 1.1482x; 1.1482x over previous
#include <cuda_runtime.h>
#include <cuda_fp16.h>
#include <cstdint>
#include <cstddef>

constexpr int BATCH = 4, SEQ = 2048, DI = 4096, DO = 4096, RANK = 16;
constexpr int MTOT = BATCH * SEQ;          // 8192
constexpr float LORA_SCALE = 2.0f;         // ALPHA / RANK

constexpr int TM = 128, TN = 256, KC = 64; // K-chunk = 64 fp16 = 128B rows
constexpr int STAGES = 4;
constexpr int NCHUNK = DI / KC;            // 64 real chunks; chunk 64 = LoRA chunk
constexpr int A_BYTES = TM * 128;          // 16 KB
constexpr int B_BYTES = TN * 128;          // 32 KB
constexpr int STAGE_BYTES = A_BYTES + B_BYTES;           // 48 KB
constexpr int SMEM_BYTES = 1024 + STAGES * STAGE_BYTES;  // 197632

// Row swizzle over 16B chunk index (3 bits), conflict-free for v4 frag loads.
#define SWZ(r) (((((r) & 1) << 2) | (((r) >> 1) & 3)))

// ---------------- scratch (__device__ globals: allocation-free) -------------
// fp16 operands, permuted per 64-k group (see prior rounds).
__device__ __align__(128) __half g_xp[(size_t)MTOT * DI];
__device__ __align__(128) __half g_wp[(size_t)DO * DI];
__device__ __align__(128) float  g_downw[BATCH * RANK * DI];      // fp32, scale folded
__device__ __align__(128) __half g_upp[(size_t)BATCH * DO * 64];  // K padded 64, perm
__device__ __align__(128) __half g_lrp[(size_t)MTOT * 64];        // K padded 64, perm

#define DEVFN __device__ __forceinline__

DEVFN uint32_t s2u(const void* p) {
    uint32_t a;
    asm("{ .reg .u64 t; cvta.to.shared.u64 t, %1; cvt.u32.u64 %0, t; }" : "=r"(a) : "l"(p));
    return a;
}
DEVFN void cp_async16(uint32_t dst, const void* src) {
    unsigned long long g = (unsigned long long)__cvta_generic_to_global((void*)src);
    asm volatile("cp.async.cg.shared.global [%0], [%1], 16;" :: "r"(dst), "l"(g));
}
#define CP_COMMIT() asm volatile("cp.async.commit_group;" ::: "memory")

DEVFN uint4 lds_v4u(uint32_t addr) {
    uint4 v;
    asm volatile("ld.shared.v4.b32 {%0,%1,%2,%3}, [%4];"
                 : "=r"(v.x), "=r"(v.y), "=r"(v.z), "=r"(v.w) : "r"(addr));
    return v;
}

// fp32-accumulate HMMA
DEVFN void mma16(float* d, uint32_t a0, uint32_t a1, uint32_t a2, uint32_t a3,
                 uint32_t b0, uint32_t b1) {
    asm volatile("mma.sync.aligned.m16n8k16.row.col.f32.f16.f16.f32 "
                 "{%0,%1,%2,%3}, {%4,%5,%6,%7}, {%8,%9}, {%0,%1,%2,%3};"
                 : "+f"(d[0]), "+f"(d[1]), "+f"(d[2]), "+f"(d[3])
                 : "r"(a0), "r"(a1), "r"(a2), "r"(a3), "r"(b0), "r"(b1));
}

DEVFN uint32_t h2u(__half2 h) { return *reinterpret_cast<uint32_t*>(&h); }

// ------------------------- merged prep kernel (round-10 measured) -----------
// blocks [0,64): down factors; [64,128): up factors; [128,4224): W convert
__global__ __launch_bounds__(256) void prep_all_kernel(
    const float* __restrict__ da, const float* __restrict__ ua,
    const float* __restrict__ hd, const float* __restrict__ hu,
    const float* __restrict__ W)
{
    __shared__ float hs[1024];
    const int bid = blockIdx.x, t = threadIdx.x;
    if (bid < 64) {
        const int b = bid >> 4;
        const int i = (bid & 15) * 256 + t;
        for (int j = t; j < 1024; j += 256) hs[j] = hd[b * 1024 + j];  // hs[a*16+r]
        __syncthreads();
        float acc[16];
        #pragma unroll
        for (int r = 0; r < 16; r++) acc[r] = 0.f;
        const float4* dap = reinterpret_cast<const float4*>(da + (size_t)i * 64);
        #pragma unroll 4
        for (int aq = 0; aq < 16; aq++) {
            float4 v = dap[aq];
            #pragma unroll
            for (int r = 0; r < 16; r++)
                acc[r] += v.x * hs[(aq * 4 + 0) * 16 + r] + v.y * hs[(aq * 4 + 1) * 16 + r]
                        + v.z * hs[(aq * 4 + 2) * 16 + r] + v.w * hs[(aq * 4 + 3) * 16 + r];
        }
        #pragma unroll
        for (int r = 0; r < 16; r++)
            g_downw[((size_t)b * RANK + r) * DI + i] = LORA_SCALE * acc[r];
    } else if (bid < 128) {
        const int bb2 = bid - 64;
        const int b = bb2 >> 4;
        const int o = (bb2 & 15) * 256 + t;
        for (int j = t; j < 1024; j += 256) hs[j] = hu[b * 1024 + j];  // hs[c*64+a]
        __syncthreads();
        float acc[16];
        #pragma unroll
        for (int c = 0; c < 16; c++) acc[c] = 0.f;
        #pragma unroll 4
        for (int a = 0; a < 64; a++) {
            float uv = ua[(size_t)a * DO + o];
            #pragma unroll
            for (int c = 0; c < 16; c++) acc[c] += uv * hs[c * 64 + a];
        }
        __half* op = g_upp + ((size_t)b * DO + o) * 64;
        #pragma unroll
        for (int q = 0; q < 4; q++) {
            uint2 v;
            v.x = h2u(__floats2half2_rn(acc[2 * q], acc[2 * q + 1]));
            v.y = h2u(__floats2half2_rn(acc[2 * q + 8], acc[2 * q + 9]));
            *reinterpret_cast<uint2*>(op + q * 8) = v;
            *reinterpret_cast<uint2*>(op + q * 8 + 4) = make_uint2(0, 0);
        }
        #pragma unroll
        for (int q = 0; q < 4; q++)
            *reinterpret_cast<uint4*>(op + 32 + q * 8) = make_uint4(0, 0, 0, 0);
    } else {
        // W convert: one (s,G) half-supergroup (16 consecutive k) per thread
        const size_t tid = (size_t)(bid - 128) * 256 + t;
        const size_t grp = tid >> 2;
        const int off = (int)(tid & 3) * 16;
        const int sb = ((off >> 5) & 1) * 32 + ((off >> 4) & 1) * 4;
        const float* wp = W + grp * 64 + off;
        float v[16];
        #pragma unroll
        for (int q = 0; q < 4; q++) {
            float4 f = reinterpret_cast<const float4*>(wp)[q];
            v[4 * q] = f.x; v[4 * q + 1] = f.y; v[4 * q + 2] = f.z; v[4 * q + 3] = f.w;
        }
        __half* op = g_wp + grp * 64 + sb;
        #pragma unroll
        for (int g4 = 0; g4 < 4; g4++) {
            uint2 u;
            u.x = h2u(__floats2half2_rn(v[2 * g4], v[2 * g4 + 1]));
            u.y = h2u(__floats2half2_rn(v[8 + 2 * g4], v[9 + 2 * g4]));
            *reinterpret_cast<uint2*>(op + g4 * 8) = u;
        }
    }
}

// smem swizzle for down_s: XOR 16B-chunk index with (chunk>>3)&7
DEVFN int dswz(int kk) {
    int c = kk >> 2;
    return ((c ^ ((c >> 3) & 7)) << 2) | (kk & 3);
}

// Fused: x -> fp16+perm copy AND low_rank = x @ down^T (round-10 measured: 16 rows).
__global__ __launch_bounds__(256) void lowrank_kernel(const float* __restrict__ x) {
    __shared__ float down_s[16 * 512];
    const int m0 = blockIdx.x * 16;
    const int bb = m0 / SEQ;
    const int t = threadIdx.x, w = t >> 5, l = t & 31;
    const int rowbase = m0 + w * 2;
    const float* dwb = g_downw + (size_t)bb * RANK * DI;

    const int ks = l * 16;
    const int o0 = dswz(ks), o1 = dswz(ks + 4), o2 = dswz(ks + 8), o3 = dswz(ks + 12);

    float acc[2][16];
    #pragma unroll
    for (int j = 0; j < 2; j++)
        #pragma unroll
        for (int r = 0; r < 16; r++) acc[j][r] = 0.f;

    for (int k0 = 0; k0 < DI; k0 += 512) {
        __syncthreads();
        for (int j = t; j < 16 * 512; j += 256) {
            int r = j >> 9, kk = j & 511;
            down_s[r * 512 + dswz(kk)] = dwb[r * DI + k0 + kk];
        }
        __syncthreads();
        const int gk = k0 + ks;
        const int grp = gk & ~63, off = gk & 63;
        const int sb = ((off >> 5) & 1) * 32 + ((off >> 4) & 1) * 4;
        #pragma unroll
        for (int j = 0; j < 2; j++) {
            const float* xr = x + (size_t)(rowbase + j) * DI + gk;
            float v[16];
            #pragma unroll
            for (int q = 0; q < 4; q++) {
                float4 f = reinterpret_cast<const float4*>(xr)[q];
                v[4 * q] = f.x; v[4 * q + 1] = f.y; v[4 * q + 2] = f.z; v[4 * q + 3] = f.w;
            }
            __half* op = g_xp + (size_t)(rowbase + j) * DI + grp + sb;
            #pragma unroll
            for (int g4 = 0; g4 < 4; g4++) {
                uint2 u;
                u.x = h2u(__floats2half2_rn(v[2 * g4], v[2 * g4 + 1]));
                u.y = h2u(__floats2half2_rn(v[8 + 2 * g4], v[9 + 2 * g4]));
                *reinterpret_cast<uint2*>(op + g4 * 8) = u;
            }
            #pragma unroll
            for (int r = 0; r < 16; r++) {
                const float* dr = down_s + r * 512;
                float4 d0 = *reinterpret_cast<const float4*>(dr + o0);
                float4 d1 = *reinterpret_cast<const float4*>(dr + o1);
                float4 d2 = *reinterpret_cast<const float4*>(dr + o2);
                float4 d3 = *reinterpret_cast<const float4*>(dr + o3);
                acc[j][r] += v[0] * d0.x + v[1] * d0.y + v[2] * d0.z + v[3] * d0.w
                           + v[4] * d1.x + v[5] * d1.y + v[6] * d1.z + v[7] * d1.w
                           + v[8] * d2.x + v[9] * d2.y + v[10] * d2.z + v[11] * d2.w
                           + v[12] * d3.x + v[13] * d3.y + v[14] * d3.z + v[15] * d3.w;
            }
        }
    }
    #pragma unroll
    for (int j = 0; j < 2; j++) {
        #pragma unroll
        for (int r = 0; r < 16; r++) {
            float v = acc[j][r];
            v += __shfl_xor_sync(~0u, v, 16);
            v += __shfl_xor_sync(~0u, v, 8);
            v += __shfl_xor_sync(~0u, v, 4);
            v += __shfl_xor_sync(~0u, v, 2);
            v += __shfl_xor_sync(~0u, v, 1);
            acc[j][r] = v;
        }
        if (l == 0) {
            __half* op = g_lrp + (size_t)(rowbase + j) * 64;
            #pragma unroll
            for (int q = 0; q < 4; q++) {
                uint2 u;
                u.x = h2u(__floats2half2_rn(acc[j][2 * q], acc[j][2 * q + 1]));
                u.y = h2u(__floats2half2_rn(acc[j][2 * q + 8], acc[j][2 * q + 9]));
                *reinterpret_cast<uint2*>(op + q * 8) = u;
                *reinterpret_cast<uint2*>(op + q * 8 + 4) = make_uint2(0, 0);
            }
            #pragma unroll
            for (int q = 0; q < 4; q++)
                *reinterpret_cast<uint4*>(op + 32 + q * 8) = make_uint4(0, 0, 0, 0);
        }
    }
}

// ------------------------------- main GEMM ----------------------------------
// 256 threads, 8 warps (2x4), warp tile 64x64, fp16 m16n8k16, 4 stages.
// All hot-loop addresses reduced to  base_reg + compile-time immediate.

// real-chunk loads: pA/pB point at this thread's (row,ch) element of chunk c
DEVFN void load_fast(uint32_t sdstA, uint32_t sdstB,
                     const __half* pA, const __half* pB) {
    #pragma unroll
    for (int q = 0; q < 4; q++)                    // A rows: t>>3 + q*32
        cp_async16(sdstA + q * 4096, pA + (size_t)q * 32 * DI);
    #pragma unroll
    for (int q = 0; q < 8; q++)                    // B rows: t>>3 + q*32
        cp_async16(sdstB + q * 4096, pB + (size_t)q * 32 * DI);
}

// LoRA tail (stride-64 source, zero-padded K 32..63)
DEVFN void load_tail(uint32_t sdstA, uint32_t sdstB, int m0, int n0, int bb, int t) {
    const int ro = (t >> 3) * 64 + (t & 7) * 8;
    const __half* ap = g_lrp + (size_t)m0 * 64 + ro;
    const __half* bp = g_upp + ((size_t)bb * DO + n0) * 64 + ro;
    #pragma unroll
    for (int q = 0; q < 4; q++)
        cp_async16(sdstA + q * 4096, ap + q * 32 * 64);
    #pragma unroll
    for (int q = 0; q < 8; q++)
        cp_async16(sdstB + q * 4096, bp + q * 32 * 64);
}

DEVFN void compute_chunk(uint32_t sbase, uint32_t aOff0, uint32_t bOff0,
                         float acc[4][8][4]) {
    #pragma unroll
    for (int s = 0; s < 2; s++) {
        const uint32_t aB = sbase + (s ? (aOff0 ^ 64u) : aOff0);
        const uint32_t bB = sbase + (s ? (bOff0 ^ 64u) : bOff0);
        uint4 A0[4], A1[4];
        #pragma unroll
        for (int mf = 0; mf < 4; mf++) {
            A0[mf] = lds_v4u(aB + mf * 2048);
            A1[mf] = lds_v4u(aB + mf * 2048 + 1024);
        }
        #pragma unroll
        for (int half = 0; half < 2; half++) {
            uint4 Bf[4];
            #pragma unroll
            for (int j = 0; j < 4; j++)
                Bf[j] = lds_v4u(bB + (half * 4 + j) * 1024);
            #pragma unroll
            for (int mf = 0; mf < 4; mf++)
                #pragma unroll
                for (int j = 0; j < 4; j++) {
                    float* d = acc[mf][half * 4 + j];
                    mma16(d, A0[mf].x, A1[mf].x, A0[mf].y, A1[mf].y,
                          Bf[j].x, Bf[j].y);
                    mma16(d, A0[mf].z, A1[mf].z, A0[mf].w, A1[mf].w,
                          Bf[j].z, Bf[j].w);
                }
        }
    }
}

#define WAITG(n) asm volatile("cp.async.wait_group " #n ";" ::: "memory")

__global__ void __launch_bounds__(256, 1)
gemm_kernel(const float* __restrict__ bias, float* __restrict__ out) {
    extern __shared__ char smem_raw[];
    float* bias_s = reinterpret_cast<float*>(smem_raw);   // 256 floats
    const uint32_t stage_u = s2u(smem_raw + 1024);

    const int t = threadIdx.x;
    const int wid = t >> 5, lane = t & 31;
    const int gID = lane >> 2, g = lane & 3;
    const int warpM = wid >> 2, warpN = wid & 3;          // 2 x 4 warps, 64x64 tiles

    const int n0 = blockIdx.x * TN;
    const int m0 = blockIdx.y * TM;
    const int bb = m0 / SEQ;

    bias_s[t] = bias[n0 + t];

    // loop-invariant LDS fragment bases (row&7 == gID for every fragment row)
    const uint32_t swzg = (uint32_t)((g ^ SWZ(gID)) << 4);
    const uint32_t aOff0 = (uint32_t)(warpM * 8192 + gID * 128) + swzg;
    const uint32_t bOff0 = (uint32_t)A_BYTES + (uint32_t)(warpN * 8192 + gID * 128) + swzg;

    // loop-invariant cp.async dst base (row = t>>3 + q*32, ch = t&7)
    const uint32_t dSwz = (uint32_t)((t >> 3) * 128)
                        + (uint32_t)((((t & 7) ^ SWZ((t >> 3) & 7))) << 4);
    uint32_t stA[4], stB[4], cstg[4];
    #pragma unroll
    for (int s = 0; s < 4; s++) {
        cstg[s] = stage_u + s * STAGE_BYTES;
        stA[s] = cstg[s] + dSwz;
        stB[s] = stA[s] + A_BYTES;
    }

    // global src base for this thread (advances by KC per chunk)
    const int gro = (t >> 3) * DI + (t & 7) * 8;
    const __half* pA0 = g_xp + (size_t)m0 * DI + gro;
    const __half* pB0 = g_wp + (size_t)n0 * DI + gro;

    float acc[4][8][4];
    #pragma unroll
    for (int mf = 0; mf < 4; mf++)
        #pragma unroll
        for (int nf = 0; nf < 8; nf++)
            #pragma unroll
            for (int k = 0; k < 4; k++) acc[mf][nf][k] = 0.f;

    load_fast(stA[0], stB[0], pA0, pB0);                   CP_COMMIT();
    load_fast(stA[1], stB[1], pA0 + KC, pB0 + KC);         CP_COMMIT();
    load_fast(stA[2], stB[2], pA0 + 2 * KC, pB0 + 2 * KC); CP_COMMIT();
    const __half* pAd = pA0 + 3 * KC;
    const __half* pBd = pB0 + 3 * KC;

    // main loop: chunks 0..59, unrolled by 4 so stage indices are immediates
    for (int c4 = 0; c4 < 60; c4 += 4) {
        #pragma unroll
        for (int u = 0; u < 4; u++) {
            WAITG(2);
            __syncthreads();
            load_fast(stA[(u + 3) & 3], stB[(u + 3) & 3], pAd, pBd);
            CP_COMMIT();
            pAd += KC; pBd += KC;
            compute_chunk(cstg[u], aOff0, bOff0, acc);
        }
    }
    // peeled tail: chunks 60..63 + LoRA chunk 64
    WAITG(2); __syncthreads();                              // c=60
    load_fast(stA[3], stB[3], pAd, pBd); CP_COMMIT();       // prefetch 63
    compute_chunk(cstg[0], aOff0, bOff0, acc);
    WAITG(2); __syncthreads();                              // c=61
    load_tail(stA[0], stB[0], m0, n0, bb, t); CP_COMMIT();  // prefetch 64 (LoRA)
    compute_chunk(cstg[1], aOff0, bOff0, acc);
    WAITG(2); __syncthreads();                              // c=62
    compute_chunk(cstg[2], aOff0, bOff0, acc);
    WAITG(1); __syncthreads();                              // c=63
    compute_chunk(cstg[3], aOff0, bOff0, acc);
    WAITG(0); __syncthreads();                              // c=64 (LoRA)
    compute_chunk(cstg[0], aOff0, bOff0, acc);

    // epilogue: c0:(gID, 2g) c1:(gID, 2g+1) c2:(gID+8, 2g) c3:(gID+8, 2g+1)
    #pragma unroll
    for (int mf = 0; mf < 4; mf++) {
        const int r0 = m0 + warpM * 64 + mf * 16 + gID;
        #pragma unroll
        for (int nf = 0; nf < 8; nf++) {
            const int col = warpN * 64 + nf * 8 + 2 * g;
            const float b0 = bias_s[col], b1 = bias_s[col + 1];
            float2 v0, v1;
            v0.x = acc[mf][nf][0] + b0; v0.y = acc[mf][nf][1] + b1;
            v1.x = acc[mf][nf][2] + b0; v1.y = acc[mf][nf][3] + b1;
            *reinterpret_cast<float2*>(out + (size_t)r0 * DO + n0 + col) = v0;
            *reinterpret_cast<float2*>(out + (size_t)(r0 + 8) * DO + n0 + col) = v1;
        }
    }
}

// ------------------------------- launch -------------------------------------
extern "C" void kernel_launch(void* const* d_in, const int* /*in_sizes*/, int /*n_in*/,
                              void* d_out, int /*out_size*/) {
    const float* x  = (const float*)d_in[0];
    const float* W  = (const float*)d_in[1];
    const float* b  = (const float*)d_in[2];
    const float* da = (const float*)d_in[3];
    const float* ua = (const float*)d_in[4];
    const float* hd = (const float*)d_in[5];
    const float* hu = (const float*)d_in[6];
    float* out = (float*)d_out;

    cudaFuncSetAttribute(gemm_kernel, cudaFuncAttributeMaxDynamicSharedMemorySize, SMEM_BYTES);

    prep_all_kernel<<<128 + DO * DI / 16 / 256, 256>>>(da, ua, hd, hu, W);
    lowrank_kernel<<<MTOT / 16, 256>>>(x);
    gemm_kernel<<<dim3(DO / TN, MTOT / TM), 256, SMEM_BYTES>>>(b, out);
}

// round 13
// speedup vs baseline: 1.1493x; 1.0010x over previous
#include <cuda_runtime.h>
#include <cuda_fp16.h>
#include <cstdint>
#include <cstddef>

constexpr int BATCH = 4, SEQ = 2048, DI = 4096, DO = 4096, RANK = 16;
constexpr int MTOT = BATCH * SEQ;          // 8192
constexpr float LORA_SCALE = 2.0f;         // ALPHA / RANK

constexpr int TM = 256, TN = 128, KC = 64; // K-chunk = 64 fp16 = 128B rows
constexpr int STAGES = 4;
constexpr int NCHUNK = DI / KC;            // 64 real chunks; chunk 64 = LoRA chunk
constexpr int A_BYTES = TM * 128;          // 32 KB
constexpr int B_BYTES = TN * 128;          // 16 KB
constexpr int STAGE_BYTES = A_BYTES + B_BYTES;           // 48 KB
constexpr int SMEM_BYTES = 1024 + STAGES * STAGE_BYTES;  // 197632

// Row swizzle over 16B chunk index (3 bits), conflict-free for v4 frag loads.
#define SWZ(r) (((((r) & 1) << 2) | (((r) >> 1) & 3)))

// ---------------- scratch (__device__ globals: allocation-free) -------------
// fp16 operands, permuted per 64-k group (see prior rounds).
__device__ __align__(128) __half g_xp[(size_t)MTOT * DI];
__device__ __align__(128) __half g_wp[(size_t)DO * DI];
__device__ __align__(128) float  g_downw[BATCH * RANK * DI];      // fp32, scale folded
__device__ __align__(128) __half g_upp[(size_t)BATCH * DO * 64];  // K padded 64, perm
__device__ __align__(128) __half g_lrp[(size_t)MTOT * 64];        // K padded 64, perm

#define DEVFN __device__ __forceinline__

DEVFN uint32_t s2u(const void* p) {
    uint32_t a;
    asm("{ .reg .u64 t; cvta.to.shared.u64 t, %1; cvt.u32.u64 %0, t; }" : "=r"(a) : "l"(p));
    return a;
}
DEVFN void cp_async16(uint32_t dst, const void* src) {
    unsigned long long g = (unsigned long long)__cvta_generic_to_global((void*)src);
    asm volatile("cp.async.cg.shared.global [%0], [%1], 16;" :: "r"(dst), "l"(g));
}
#define CP_COMMIT() asm volatile("cp.async.commit_group;" ::: "memory")

DEVFN uint4 lds_v4u(uint32_t addr) {
    uint4 v;
    asm volatile("ld.shared.v4.b32 {%0,%1,%2,%3}, [%4];"
                 : "=r"(v.x), "=r"(v.y), "=r"(v.z), "=r"(v.w) : "r"(addr));
    return v;
}

// fp32-accumulate HMMA
DEVFN void mma16(float* d, uint32_t a0, uint32_t a1, uint32_t a2, uint32_t a3,
                 uint32_t b0, uint32_t b1) {
    asm volatile("mma.sync.aligned.m16n8k16.row.col.f32.f16.f16.f32 "
                 "{%0,%1,%2,%3}, {%4,%5,%6,%7}, {%8,%9}, {%0,%1,%2,%3};"
                 : "+f"(d[0]), "+f"(d[1]), "+f"(d[2]), "+f"(d[3])
                 : "r"(a0), "r"(a1), "r"(a2), "r"(a3), "r"(b0), "r"(b1));
}

DEVFN uint32_t h2u(__half2 h) { return *reinterpret_cast<uint32_t*>(&h); }

// ------------------------- merged prep kernel (round-10 measured) -----------
// blocks [0,64): down factors; [64,128): up factors; [128,4224): W convert
__global__ __launch_bounds__(256) void prep_all_kernel(
    const float* __restrict__ da, const float* __restrict__ ua,
    const float* __restrict__ hd, const float* __restrict__ hu,
    const float* __restrict__ W)
{
    __shared__ float hs[1024];
    const int bid = blockIdx.x, t = threadIdx.x;
    if (bid < 64) {
        const int b = bid >> 4;
        const int i = (bid & 15) * 256 + t;
        for (int j = t; j < 1024; j += 256) hs[j] = hd[b * 1024 + j];  // hs[a*16+r]
        __syncthreads();
        float acc[16];
        #pragma unroll
        for (int r = 0; r < 16; r++) acc[r] = 0.f;
        const float4* dap = reinterpret_cast<const float4*>(da + (size_t)i * 64);
        #pragma unroll 4
        for (int aq = 0; aq < 16; aq++) {
            float4 v = dap[aq];
            #pragma unroll
            for (int r = 0; r < 16; r++)
                acc[r] += v.x * hs[(aq * 4 + 0) * 16 + r] + v.y * hs[(aq * 4 + 1) * 16 + r]
                        + v.z * hs[(aq * 4 + 2) * 16 + r] + v.w * hs[(aq * 4 + 3) * 16 + r];
        }
        #pragma unroll
        for (int r = 0; r < 16; r++)
            g_downw[((size_t)b * RANK + r) * DI + i] = LORA_SCALE * acc[r];
    } else if (bid < 128) {
        const int bb2 = bid - 64;
        const int b = bb2 >> 4;
        const int o = (bb2 & 15) * 256 + t;
        for (int j = t; j < 1024; j += 256) hs[j] = hu[b * 1024 + j];  // hs[c*64+a]
        __syncthreads();
        float acc[16];
        #pragma unroll
        for (int c = 0; c < 16; c++) acc[c] = 0.f;
        #pragma unroll 4
        for (int a = 0; a < 64; a++) {
            float uv = ua[(size_t)a * DO + o];
            #pragma unroll
            for (int c = 0; c < 16; c++) acc[c] += uv * hs[c * 64 + a];
        }
        __half* op = g_upp + ((size_t)b * DO + o) * 64;
        #pragma unroll
        for (int q = 0; q < 4; q++) {
            uint2 v;
            v.x = h2u(__floats2half2_rn(acc[2 * q], acc[2 * q + 1]));
            v.y = h2u(__floats2half2_rn(acc[2 * q + 8], acc[2 * q + 9]));
            *reinterpret_cast<uint2*>(op + q * 8) = v;
            *reinterpret_cast<uint2*>(op + q * 8 + 4) = make_uint2(0, 0);
        }
        #pragma unroll
        for (int q = 0; q < 4; q++)
            *reinterpret_cast<uint4*>(op + 32 + q * 8) = make_uint4(0, 0, 0, 0);
    } else {
        // W convert: one (s,G) half-supergroup (16 consecutive k) per thread
        const size_t tid = (size_t)(bid - 128) * 256 + t;
        const size_t grp = tid >> 2;
        const int off = (int)(tid & 3) * 16;
        const int sb = ((off >> 5) & 1) * 32 + ((off >> 4) & 1) * 4;
        const float* wp = W + grp * 64 + off;
        float v[16];
        #pragma unroll
        for (int q = 0; q < 4; q++) {
            float4 f = reinterpret_cast<const float4*>(wp)[q];
            v[4 * q] = f.x; v[4 * q + 1] = f.y; v[4 * q + 2] = f.z; v[4 * q + 3] = f.w;
        }
        __half* op = g_wp + grp * 64 + sb;
        #pragma unroll
        for (int g4 = 0; g4 < 4; g4++) {
            uint2 u;
            u.x = h2u(__floats2half2_rn(v[2 * g4], v[2 * g4 + 1]));
            u.y = h2u(__floats2half2_rn(v[8 + 2 * g4], v[9 + 2 * g4]));
            *reinterpret_cast<uint2*>(op + g4 * 8) = u;
        }
    }
}

// smem swizzle for down_s: XOR 16B-chunk index with (chunk>>3)&7
DEVFN int dswz(int kk) {
    int c = kk >> 2;
    return ((c ^ ((c >> 3) & 7)) << 2) | (kk & 3);
}

// Fused: x -> fp16+perm copy AND low_rank = x @ down^T (round-10 measured: 16 rows).
__global__ __launch_bounds__(256) void lowrank_kernel(const float* __restrict__ x) {
    __shared__ float down_s[16 * 512];
    const int m0 = blockIdx.x * 16;
    const int bb = m0 / SEQ;
    const int t = threadIdx.x, w = t >> 5, l = t & 31;
    const int rowbase = m0 + w * 2;
    const float* dwb = g_downw + (size_t)bb * RANK * DI;

    const int ks = l * 16;
    const int o0 = dswz(ks), o1 = dswz(ks + 4), o2 = dswz(ks + 8), o3 = dswz(ks + 12);

    float acc[2][16];
    #pragma unroll
    for (int j = 0; j < 2; j++)
        #pragma unroll
        for (int r = 0; r < 16; r++) acc[j][r] = 0.f;

    for (int k0 = 0; k0 < DI; k0 += 512) {
        __syncthreads();
        for (int j = t; j < 16 * 512; j += 256) {
            int r = j >> 9, kk = j & 511;
            down_s[r * 512 + dswz(kk)] = dwb[r * DI + k0 + kk];
        }
        __syncthreads();
        const int gk = k0 + ks;
        const int grp = gk & ~63, off = gk & 63;
        const int sb = ((off >> 5) & 1) * 32 + ((off >> 4) & 1) * 4;
        #pragma unroll
        for (int j = 0; j < 2; j++) {
            const float* xr = x + (size_t)(rowbase + j) * DI + gk;
            float v[16];
            #pragma unroll
            for (int q = 0; q < 4; q++) {
                float4 f = reinterpret_cast<const float4*>(xr)[q];
                v[4 * q] = f.x; v[4 * q + 1] = f.y; v[4 * q + 2] = f.z; v[4 * q + 3] = f.w;
            }
            __half* op = g_xp + (size_t)(rowbase + j) * DI + grp + sb;
            #pragma unroll
            for (int g4 = 0; g4 < 4; g4++) {
                uint2 u;
                u.x = h2u(__floats2half2_rn(v[2 * g4], v[2 * g4 + 1]));
                u.y = h2u(__floats2half2_rn(v[8 + 2 * g4], v[9 + 2 * g4]));
                *reinterpret_cast<uint2*>(op + g4 * 8) = u;
            }
            #pragma unroll
            for (int r = 0; r < 16; r++) {
                const float* dr = down_s + r * 512;
                float4 d0 = *reinterpret_cast<const float4*>(dr + o0);
                float4 d1 = *reinterpret_cast<const float4*>(dr + o1);
                float4 d2 = *reinterpret_cast<const float4*>(dr + o2);
                float4 d3 = *reinterpret_cast<const float4*>(dr + o3);
                acc[j][r] += v[0] * d0.x + v[1] * d0.y + v[2] * d0.z + v[3] * d0.w
                           + v[4] * d1.x + v[5] * d1.y + v[6] * d1.z + v[7] * d1.w
                           + v[8] * d2.x + v[9] * d2.y + v[10] * d2.z + v[11] * d2.w
                           + v[12] * d3.x + v[13] * d3.y + v[14] * d3.z + v[15] * d3.w;
            }
        }
    }
    #pragma unroll
    for (int j = 0; j < 2; j++) {
        #pragma unroll
        for (int r = 0; r < 16; r++) {
            float v = acc[j][r];
            v += __shfl_xor_sync(~0u, v, 16);
            v += __shfl_xor_sync(~0u, v, 8);
            v += __shfl_xor_sync(~0u, v, 4);
            v += __shfl_xor_sync(~0u, v, 2);
            v += __shfl_xor_sync(~0u, v, 1);
            acc[j][r] = v;
        }
        if (l == 0) {
            __half* op = g_lrp + (size_t)(rowbase + j) * 64;
            #pragma unroll
            for (int q = 0; q < 4; q++) {
                uint2 u;
                u.x = h2u(__floats2half2_rn(acc[j][2 * q], acc[j][2 * q + 1]));
                u.y = h2u(__floats2half2_rn(acc[j][2 * q + 8], acc[j][2 * q + 9]));
                *reinterpret_cast<uint2*>(op + q * 8) = u;
                *reinterpret_cast<uint2*>(op + q * 8 + 4) = make_uint2(0, 0);
            }
            #pragma unroll
            for (int q = 0; q < 4; q++)
                *reinterpret_cast<uint4*>(op + 32 + q * 8) = make_uint4(0, 0, 0, 0);
        }
    }
}

// ------------------------------- main GEMM ----------------------------------
// 512 threads, 16 warps (4x4), warp tile 64x32, fp16 m16n8k16, 4 stages.
// All hot-loop addresses are base_reg + compile-time immediate.

DEVFN void load_fast(uint32_t sdstA, uint32_t sdstB,
                     const __half* pA, const __half* pB) {
    #pragma unroll
    for (int q = 0; q < 4; q++)                    // A rows: t>>3 + q*64 (256 rows)
        cp_async16(sdstA + q * 8192, pA + (size_t)q * 64 * DI);
    #pragma unroll
    for (int q = 0; q < 2; q++)                    // B rows: t>>3 + q*64 (128 rows)
        cp_async16(sdstB + q * 8192, pB + (size_t)q * 64 * DI);
}

// LoRA tail (stride-64 source, zero-padded K 32..63)
DEVFN void load_tail(uint32_t sdstA, uint32_t sdstB, int m0, int n0, int bb, int t) {
    const int ro = (t >> 3) * 64 + (t & 7) * 8;
    const __half* ap = g_lrp + (size_t)m0 * 64 + ro;
    const __half* bp = g_upp + ((size_t)bb * DO + n0) * 64 + ro;
    #pragma unroll
    for (int q = 0; q < 4; q++)
        cp_async16(sdstA + q * 8192, ap + q * 64 * 64);
    #pragma unroll
    for (int q = 0; q < 2; q++)
        cp_async16(sdstB + q * 8192, bp + q * 64 * 64);
}

DEVFN void compute_chunk(uint32_t sbase, uint32_t aOff0, uint32_t bOff0,
                         float acc[4][4][4]) {
    #pragma unroll
    for (int s = 0; s < 2; s++) {
        const uint32_t aB = sbase + (s ? (aOff0 ^ 64u) : aOff0);
        const uint32_t bB = sbase + (s ? (bOff0 ^ 64u) : bOff0);
        uint4 Bf[4];
        #pragma unroll
        for (int j = 0; j < 4; j++)
            Bf[j] = lds_v4u(bB + j * 1024);
        #pragma unroll
        for (int mf = 0; mf < 4; mf++) {
            uint4 A0 = lds_v4u(aB + mf * 2048);
            uint4 A1 = lds_v4u(aB + mf * 2048 + 1024);
            #pragma unroll
            for (int j = 0; j < 4; j++) {
                float* d = acc[mf][j];
                mma16(d, A0.x, A1.x, A0.y, A1.y, Bf[j].x, Bf[j].y);
                mma16(d, A0.z, A1.z, A0.w, A1.w, Bf[j].z, Bf[j].w);
            }
        }
    }
}

#define WAITG(n) asm volatile("cp.async.wait_group " #n ";" ::: "memory")

__global__ void __launch_bounds__(512, 1)
gemm_kernel(const float* __restrict__ bias, float* __restrict__ out) {
    extern __shared__ char smem_raw[];
    float* bias_s = reinterpret_cast<float*>(smem_raw);   // 128 floats
    const uint32_t stage_u = s2u(smem_raw + 1024);

    const int t = threadIdx.x;
    const int wid = t >> 5, lane = t & 31;
    const int gID = lane >> 2, g = lane & 3;
    const int warpM = wid >> 2, warpN = wid & 3;          // 4 x 4 warps, 64x32 tiles

    const int n0 = blockIdx.x * TN;
    const int m0 = blockIdx.y * TM;
    const int bb = m0 / SEQ;

    if (t < TN) bias_s[t] = bias[n0 + t];

    // loop-invariant LDS fragment bases (row&7 == gID for every fragment row)
    const uint32_t swzg = (uint32_t)((g ^ SWZ(gID)) << 4);
    const uint32_t aOff0 = (uint32_t)(warpM * 8192 + gID * 128) + swzg;
    const uint32_t bOff0 = (uint32_t)A_BYTES + (uint32_t)(warpN * 4096 + gID * 128) + swzg;

    // loop-invariant cp.async dst base (row = t>>3 + q*64, ch = t&7)
    const uint32_t dSwz = (uint32_t)((t >> 3) * 128)
                        + (uint32_t)((((t & 7) ^ SWZ((t >> 3) & 7))) << 4);
    uint32_t stA[4], stB[4], cstg[4];
    #pragma unroll
    for (int s = 0; s < 4; s++) {
        cstg[s] = stage_u + s * STAGE_BYTES;
        stA[s] = cstg[s] + dSwz;
        stB[s] = stA[s] + A_BYTES;
    }

    // global src base for this thread (advances by KC per chunk)
    const int gro = (t >> 3) * DI + (t & 7) * 8;
    const __half* pA0 = g_xp + (size_t)m0 * DI + gro;
    const __half* pB0 = g_wp + (size_t)n0 * DI + gro;

    float acc[4][4][4];
    #pragma unroll
    for (int mf = 0; mf < 4; mf++)
        #pragma unroll
        for (int nf = 0; nf < 4; nf++)
            #pragma unroll
            for (int k = 0; k < 4; k++) acc[mf][nf][k] = 0.f;

    load_fast(stA[0], stB[0], pA0, pB0);                   CP_COMMIT();
    load_fast(stA[1], stB[1], pA0 + KC, pB0 + KC);         CP_COMMIT();
    load_fast(stA[2], stB[2], pA0 + 2 * KC, pB0 + 2 * KC); CP_COMMIT();
    const __half* pAd = pA0 + 3 * KC;
    const __half* pBd = pB0 + 3 * KC;

    // main loop: chunks 0..59, unrolled by 4 so stage indices are immediates
    for (int c4 = 0; c4 < 60; c4 += 4) {
        #pragma unroll
        for (int u = 0; u < 4; u++) {
            WAITG(2);
            __syncthreads();
            load_fast(stA[(u + 3) & 3], stB[(u + 3) & 3], pAd, pBd);
            CP_COMMIT();
            pAd += KC; pBd += KC;
            compute_chunk(cstg[u], aOff0, bOff0, acc);
        }
    }
    // peeled tail: chunks 60..63 + LoRA chunk 64
    WAITG(2); __syncthreads();                              // c=60
    load_fast(stA[3], stB[3], pAd, pBd); CP_COMMIT();       // prefetch 63
    compute_chunk(cstg[0], aOff0, bOff0, acc);
    WAITG(2); __syncthreads();                              // c=61
    load_tail(stA[0], stB[0], m0, n0, bb, t); CP_COMMIT();  // prefetch 64 (LoRA)
    compute_chunk(cstg[1], aOff0, bOff0, acc);
    WAITG(2); __syncthreads();                              // c=62
    compute_chunk(cstg[2], aOff0, bOff0, acc);
    WAITG(1); __syncthreads();                              // c=63
    compute_chunk(cstg[3], aOff0, bOff0, acc);
    WAITG(0); __syncthreads();                              // c=64 (LoRA)
    compute_chunk(cstg[0], aOff0, bOff0, acc);

    // epilogue: c0:(gID, 2g) c1:(gID, 2g+1) c2:(gID+8, 2g) c3:(gID+8, 2g+1)
    #pragma unroll
    for (int mf = 0; mf < 4; mf++) {
        const int r0 = m0 + warpM * 64 + mf * 16 + gID;
        #pragma unroll
        for (int nf = 0; nf < 4; nf++) {
            const int col = warpN * 32 + nf * 8 + 2 * g;
            const float b0 = bias_s[col], b1 = bias_s[col + 1];
            float2 v0, v1;
            v0.x = acc[mf][nf][0] + b0; v0.y = acc[mf][nf][1] + b1;
            v1.x = acc[mf][nf][2] + b0; v1.y = acc[mf][nf][3] + b1;
            *reinterpret_cast<float2*>(out + (size_t)r0 * DO + n0 + col) = v0;
            *reinterpret_cast<float2*>(out + (size_t)(r0 + 8) * DO + n0 + col) = v1;
        }
    }
}

// ------------------------------- launch -------------------------------------
extern "C" void kernel_launch(void* const* d_in, const int* /*in_sizes*/, int /*n_in*/,
                              void* d_out, int /*out_size*/) {
    const float* x  = (const float*)d_in[0];
    const float* W  = (const float*)d_in[1];
    const float* b  = (const float*)d_in[2];
    const float* da = (const float*)d_in[3];
    const float* ua = (const float*)d_in[4];
    const float* hd = (const float*)d_in[5];
    const float* hu = (const float*)d_in[6];
    float* out = (float*)d_out;

    cudaFuncSetAttribute(gemm_kernel, cudaFuncAttributeMaxDynamicSharedMemorySize, SMEM_BYTES);

    prep_all_kernel<<<128 + DO * DI / 16 / 256, 256>>>(da, ua, hd, hu, W);
    lowrank_kernel<<<MTOT / 16, 256>>>(x);
    gemm_kernel<<<dim3(DO / TN, MTOT / TM), 512, SMEM_BYTES>>>(b, out);
}

// round 14
// speedup vs baseline: 1.1636x; 1.0125x over previous
#include <cuda_runtime.h>
#include <cuda_fp16.h>
#include <cstdint>
#include <cstddef>

constexpr int BATCH = 4, SEQ = 2048, DI = 4096, DO = 4096, RANK = 16;
constexpr int MTOT = BATCH * SEQ;          // 8192
constexpr float LORA_SCALE = 2.0f;         // ALPHA / RANK

constexpr int TM = 256, TN = 128, KC = 64; // K-chunk = 64 fp16 = 128B rows
constexpr int STAGES = 4;
constexpr int NCHUNK = DI / KC;            // 64 real chunks; chunk 64 = LoRA chunk
constexpr int A_BYTES = TM * 128;          // 32 KB
constexpr int B_BYTES = TN * 128;          // 16 KB
constexpr int STAGE_BYTES = A_BYTES + B_BYTES;           // 48 KB
constexpr int SMEM_BYTES = 1024 + STAGES * STAGE_BYTES;  // 197632

// Row swizzle over 16B chunk index (3 bits), conflict-free for v4 frag loads.
#define SWZ(r) (((((r) & 1) << 2) | (((r) >> 1) & 3)))

// ---------------- scratch (__device__ globals: allocation-free) -------------
// fp16 operands, permuted per 64-k group (see prior rounds).
__device__ __align__(128) __half g_xp[(size_t)MTOT * DI];
__device__ __align__(128) __half g_wp[(size_t)DO * DI];
__device__ __align__(128) __half g_downh[BATCH * RANK * DI];      // fp16, scale folded
__device__ __align__(128) __half g_upp[(size_t)BATCH * DO * 64];  // K padded 64, perm
__device__ __align__(128) __half g_lrp[(size_t)MTOT * 64];        // K padded 64, perm

#define DEVFN __device__ __forceinline__

DEVFN uint32_t s2u(const void* p) {
    uint32_t a;
    asm("{ .reg .u64 t; cvta.to.shared.u64 t, %1; cvt.u32.u64 %0, t; }" : "=r"(a) : "l"(p));
    return a;
}
DEVFN void cp_async16(uint32_t dst, const void* src) {
    unsigned long long g = (unsigned long long)__cvta_generic_to_global((void*)src);
    asm volatile("cp.async.cg.shared.global [%0], [%1], 16;" :: "r"(dst), "l"(g));
}
#define CP_COMMIT() asm volatile("cp.async.commit_group;" ::: "memory")

DEVFN uint4 lds_v4u(uint32_t addr) {
    uint4 v;
    asm volatile("ld.shared.v4.b32 {%0,%1,%2,%3}, [%4];"
                 : "=r"(v.x), "=r"(v.y), "=r"(v.z), "=r"(v.w) : "r"(addr));
    return v;
}

// fp32-accumulate HMMA
DEVFN void mma16(float* d, uint32_t a0, uint32_t a1, uint32_t a2, uint32_t a3,
                 uint32_t b0, uint32_t b1) {
    asm volatile("mma.sync.aligned.m16n8k16.row.col.f32.f16.f16.f32 "
                 "{%0,%1,%2,%3}, {%4,%5,%6,%7}, {%8,%9}, {%0,%1,%2,%3};"
                 : "+f"(d[0]), "+f"(d[1]), "+f"(d[2]), "+f"(d[3])
                 : "r"(a0), "r"(a1), "r"(a2), "r"(a3), "r"(b0), "r"(b1));
}

DEVFN uint32_t h2u(__half2 h) { return *reinterpret_cast<uint32_t*>(&h); }

// ------------------------- small factors prep kernel ------------------------
// blocks [0,64): down factors (fp16 out); [64,128): up factors
__global__ __launch_bounds__(256) void prep_small_kernel(
    const float* __restrict__ da, const float* __restrict__ ua,
    const float* __restrict__ hd, const float* __restrict__ hu)
{
    __shared__ float hs[1024];
    const int bid = blockIdx.x, t = threadIdx.x;
    if (bid < 64) {
        // down[b][r][i] = scale * sum_a da[i,a] * hd[b,a,r]
        const int b = bid >> 4;
        const int i = (bid & 15) * 256 + t;
        for (int j = t; j < 1024; j += 256) hs[j] = hd[b * 1024 + j];  // hs[a*16+r]
        __syncthreads();
        float acc[16];
        #pragma unroll
        for (int r = 0; r < 16; r++) acc[r] = 0.f;
        const float4* dap = reinterpret_cast<const float4*>(da + (size_t)i * 64);
        #pragma unroll 4
        for (int aq = 0; aq < 16; aq++) {
            float4 v = dap[aq];
            #pragma unroll
            for (int r = 0; r < 16; r++)
                acc[r] += v.x * hs[(aq * 4 + 0) * 16 + r] + v.y * hs[(aq * 4 + 1) * 16 + r]
                        + v.z * hs[(aq * 4 + 2) * 16 + r] + v.w * hs[(aq * 4 + 3) * 16 + r];
        }
        #pragma unroll
        for (int r = 0; r < 16; r++)
            g_downh[((size_t)b * RANK + r) * DI + i] = __float2half(LORA_SCALE * acc[r]);
    } else {
        // up[b][o][c] = sum_a ua[a,o] * hu[b,c,a]; store fp16 permuted+padded
        const int bb2 = bid - 64;
        const int b = bb2 >> 4;
        const int o = (bb2 & 15) * 256 + t;
        for (int j = t; j < 1024; j += 256) hs[j] = hu[b * 1024 + j];  // hs[c*64+a]
        __syncthreads();
        float acc[16];
        #pragma unroll
        for (int c = 0; c < 16; c++) acc[c] = 0.f;
        #pragma unroll 4
        for (int a = 0; a < 64; a++) {
            float uv = ua[(size_t)a * DO + o];
            #pragma unroll
            for (int c = 0; c < 16; c++) acc[c] += uv * hs[c * 64 + a];
        }
        __half* op = g_upp + ((size_t)b * DO + o) * 64;
        #pragma unroll
        for (int q = 0; q < 4; q++) {
            uint2 v;
            v.x = h2u(__floats2half2_rn(acc[2 * q], acc[2 * q + 1]));
            v.y = h2u(__floats2half2_rn(acc[2 * q + 8], acc[2 * q + 9]));
            *reinterpret_cast<uint2*>(op + q * 8) = v;
            *reinterpret_cast<uint2*>(op + q * 8 + 4) = make_uint2(0, 0);
        }
        #pragma unroll
        for (int q = 0; q < 4; q++)
            *reinterpret_cast<uint4*>(op + 32 + q * 8) = make_uint4(0, 0, 0, 0);
    }
}

// ---------------------- W convert kernel (streaming) ------------------------
__global__ __launch_bounds__(256) void wconv_kernel(const float* __restrict__ W) {
    const size_t tid = (size_t)blockIdx.x * 256 + threadIdx.x;
    const size_t grp = tid >> 2;
    const int off = (int)(tid & 3) * 16;
    const int sb = ((off >> 5) & 1) * 32 + ((off >> 4) & 1) * 4;
    const float* wp = W + grp * 64 + off;
    float v[16];
    #pragma unroll
    for (int q = 0; q < 4; q++) {
        float4 f = reinterpret_cast<const float4*>(wp)[q];
        v[4 * q] = f.x; v[4 * q + 1] = f.y; v[4 * q + 2] = f.z; v[4 * q + 3] = f.w;
    }
    __half* op = g_wp + grp * 64 + sb;
    #pragma unroll
    for (int g4 = 0; g4 < 4; g4++) {
        uint2 u;
        u.x = h2u(__floats2half2_rn(v[2 * g4], v[2 * g4 + 1]));
        u.y = h2u(__floats2half2_rn(v[8 + 2 * g4], v[9 + 2 * g4]));
        *reinterpret_cast<uint2*>(op + g4 * 8) = u;
    }
}

// smem swizzle for down_s: XOR 16B-chunk index with (chunk>>3)&7
DEVFN int dswz(int kk) {
    int c = kk >> 2;
    return ((c ^ ((c >> 3) & 7)) << 2) | (kk & 3);
}

// Fused: x -> fp16+perm copy AND low_rank = x @ down^T (16 rows/block).
// down factors now fp16 in DRAM (halved stream), converted to fp32 in smem.
__global__ __launch_bounds__(256) void lowrank_kernel(const float* __restrict__ x) {
    __shared__ float down_s[16 * 512];
    const int m0 = blockIdx.x * 16;
    const int bb = m0 / SEQ;
    const int t = threadIdx.x, w = t >> 5, l = t & 31;
    const int rowbase = m0 + w * 2;
    const __half* dwb = g_downh + (size_t)bb * RANK * DI;

    const int ks = l * 16;
    const int o0 = dswz(ks), o1 = dswz(ks + 4), o2 = dswz(ks + 8), o3 = dswz(ks + 12);

    float acc[2][16];
    #pragma unroll
    for (int j = 0; j < 2; j++)
        #pragma unroll
        for (int r = 0; r < 16; r++) acc[j][r] = 0.f;

    for (int k0 = 0; k0 < DI; k0 += 512) {
        __syncthreads();
        for (int j = t; j < 16 * 512 / 2; j += 256) {
            int r = j >> 8, kk2 = (j & 255) * 2;       // 2 halves per thread-step
            __half2 hv = *reinterpret_cast<const __half2*>(dwb + r * DI + k0 + kk2);
            float2 fv = __half22float2(hv);
            down_s[r * 512 + dswz(kk2)] = fv.x;
            down_s[r * 512 + dswz(kk2 + 1)] = fv.y;
        }
        __syncthreads();
        const int gk = k0 + ks;
        const int grp = gk & ~63, off = gk & 63;
        const int sb = ((off >> 5) & 1) * 32 + ((off >> 4) & 1) * 4;
        #pragma unroll
        for (int j = 0; j < 2; j++) {
            const float* xr = x + (size_t)(rowbase + j) * DI + gk;
            float v[16];
            #pragma unroll
            for (int q = 0; q < 4; q++) {
                float4 f = reinterpret_cast<const float4*>(xr)[q];
                v[4 * q] = f.x; v[4 * q + 1] = f.y; v[4 * q + 2] = f.z; v[4 * q + 3] = f.w;
            }
            __half* op = g_xp + (size_t)(rowbase + j) * DI + grp + sb;
            #pragma unroll
            for (int g4 = 0; g4 < 4; g4++) {
                uint2 u;
                u.x = h2u(__floats2half2_rn(v[2 * g4], v[2 * g4 + 1]));
                u.y = h2u(__floats2half2_rn(v[8 + 2 * g4], v[9 + 2 * g4]));
                *reinterpret_cast<uint2*>(op + g4 * 8) = u;
            }
            #pragma unroll
            for (int r = 0; r < 16; r++) {
                const float* dr = down_s + r * 512;
                float4 d0 = *reinterpret_cast<const float4*>(dr + o0);
                float4 d1 = *reinterpret_cast<const float4*>(dr + o1);
                float4 d2 = *reinterpret_cast<const float4*>(dr + o2);
                float4 d3 = *reinterpret_cast<const float4*>(dr + o3);
                acc[j][r] += v[0] * d0.x + v[1] * d0.y + v[2] * d0.z + v[3] * d0.w
                           + v[4] * d1.x + v[5] * d1.y + v[6] * d1.z + v[7] * d1.w
                           + v[8] * d2.x + v[9] * d2.y + v[10] * d2.z + v[11] * d2.w
                           + v[12] * d3.x + v[13] * d3.y + v[14] * d3.z + v[15] * d3.w;
            }
        }
    }
    #pragma unroll
    for (int j = 0; j < 2; j++) {
        #pragma unroll
        for (int r = 0; r < 16; r++) {
            float v = acc[j][r];
            v += __shfl_xor_sync(~0u, v, 16);
            v += __shfl_xor_sync(~0u, v, 8);
            v += __shfl_xor_sync(~0u, v, 4);
            v += __shfl_xor_sync(~0u, v, 2);
            v += __shfl_xor_sync(~0u, v, 1);
            acc[j][r] = v;
        }
        if (l == 0) {
            __half* op = g_lrp + (size_t)(rowbase + j) * 64;
            #pragma unroll
            for (int q = 0; q < 4; q++) {
                uint2 u;
                u.x = h2u(__floats2half2_rn(acc[j][2 * q], acc[j][2 * q + 1]));
                u.y = h2u(__floats2half2_rn(acc[j][2 * q + 8], acc[j][2 * q + 9]));
                *reinterpret_cast<uint2*>(op + q * 8) = u;
                *reinterpret_cast<uint2*>(op + q * 8 + 4) = make_uint2(0, 0);
            }
            #pragma unroll
            for (int q = 0; q < 4; q++)
                *reinterpret_cast<uint4*>(op + 32 + q * 8) = make_uint4(0, 0, 0, 0);
        }
    }
}

// ------------------------------- main GEMM ----------------------------------
// 512 threads, 16 warps (4x4), warp tile 64x32, fp16 m16n8k16, 4 stages.
DEVFN void load_fast(uint32_t sdstA, uint32_t sdstB,
                     const __half* pA, const __half* pB) {
    #pragma unroll
    for (int q = 0; q < 4; q++)                    // A rows: t>>3 + q*64 (256 rows)
        cp_async16(sdstA + q * 8192, pA + (size_t)q * 64 * DI);
    #pragma unroll
    for (int q = 0; q < 2; q++)                    // B rows: t>>3 + q*64 (128 rows)
        cp_async16(sdstB + q * 8192, pB + (size_t)q * 64 * DI);
}

// LoRA tail (stride-64 source, zero-padded K 32..63)
DEVFN void load_tail(uint32_t sdstA, uint32_t sdstB, int m0, int n0, int bb, int t) {
    const int ro = (t >> 3) * 64 + (t & 7) * 8;
    const __half* ap = g_lrp + (size_t)m0 * 64 + ro;
    const __half* bp = g_upp + ((size_t)bb * DO + n0) * 64 + ro;
    #pragma unroll
    for (int q = 0; q < 4; q++)
        cp_async16(sdstA + q * 8192, ap + q * 64 * 64);
    #pragma unroll
    for (int q = 0; q < 2; q++)
        cp_async16(sdstB + q * 8192, bp + q * 64 * 64);
}

DEVFN void compute_chunk(uint32_t sbase, uint32_t aOff0, uint32_t bOff0,
                         float acc[4][4][4]) {
    #pragma unroll
    for (int s = 0; s < 2; s++) {
        const uint32_t aB = sbase + (s ? (aOff0 ^ 64u) : aOff0);
        const uint32_t bB = sbase + (s ? (bOff0 ^ 64u) : bOff0);
        uint4 Bf[4];
        #pragma unroll
        for (int j = 0; j < 4; j++)
            Bf[j] = lds_v4u(bB + j * 1024);
        #pragma unroll
        for (int mf = 0; mf < 4; mf++) {
            uint4 A0 = lds_v4u(aB + mf * 2048);
            uint4 A1 = lds_v4u(aB + mf * 2048 + 1024);
            #pragma unroll
            for (int j = 0; j < 4; j++) {
                float* d = acc[mf][j];
                mma16(d, A0.x, A1.x, A0.y, A1.y, Bf[j].x, Bf[j].y);
                mma16(d, A0.z, A1.z, A0.w, A1.w, Bf[j].z, Bf[j].w);
            }
        }
    }
}

#define WAITG(n) asm volatile("cp.async.wait_group " #n ";" ::: "memory")

__global__ void __launch_bounds__(512, 1)
gemm_kernel(const float* __restrict__ bias, float* __restrict__ out) {
    extern __shared__ char smem_raw[];
    float* bias_s = reinterpret_cast<float*>(smem_raw);   // 128 floats
    const uint32_t stage_u = s2u(smem_raw + 1024);

    const int t = threadIdx.x;
    const int wid = t >> 5, lane = t & 31;
    const int gID = lane >> 2, g = lane & 3;
    const int warpM = wid >> 2, warpN = wid & 3;          // 4 x 4 warps, 64x32 tiles

    const int n0 = blockIdx.x * TN;
    const int m0 = blockIdx.y * TM;
    const int bb = m0 / SEQ;

    if (t < TN) bias_s[t] = bias[n0 + t];

    const uint32_t swzg = (uint32_t)((g ^ SWZ(gID)) << 4);
    const uint32_t aOff0 = (uint32_t)(warpM * 8192 + gID * 128) + swzg;
    const uint32_t bOff0 = (uint32_t)A_BYTES + (uint32_t)(warpN * 4096 + gID * 128) + swzg;

    const uint32_t dSwz = (uint32_t)((t >> 3) * 128)
                        + (uint32_t)((((t & 7) ^ SWZ((t >> 3) & 7))) << 4);
    uint32_t stA[4], stB[4], cstg[4];
    #pragma unroll
    for (int s = 0; s < 4; s++) {
        cstg[s] = stage_u + s * STAGE_BYTES;
        stA[s] = cstg[s] + dSwz;
        stB[s] = stA[s] + A_BYTES;
    }

    const int gro = (t >> 3) * DI + (t & 7) * 8;
    const __half* pA0 = g_xp + (size_t)m0 * DI + gro;
    const __half* pB0 = g_wp + (size_t)n0 * DI + gro;

    float acc[4][4][4];
    #pragma unroll
    for (int mf = 0; mf < 4; mf++)
        #pragma unroll
        for (int nf = 0; nf < 4; nf++)
            #pragma unroll
            for (int k = 0; k < 4; k++) acc[mf][nf][k] = 0.f;

    load_fast(stA[0], stB[0], pA0, pB0);                   CP_COMMIT();
    load_fast(stA[1], stB[1], pA0 + KC, pB0 + KC);         CP_COMMIT();
    load_fast(stA[2], stB[2], pA0 + 2 * KC, pB0 + 2 * KC); CP_COMMIT();
    const __half* pAd = pA0 + 3 * KC;
    const __half* pBd = pB0 + 3 * KC;

    for (int c4 = 0; c4 < 60; c4 += 4) {
        #pragma unroll
        for (int u = 0; u < 4; u++) {
            WAITG(2);
            __syncthreads();
            load_fast(stA[(u + 3) & 3], stB[(u + 3) & 3], pAd, pBd);
            CP_COMMIT();
            pAd += KC; pBd += KC;
            compute_chunk(cstg[u], aOff0, bOff0, acc);
        }
    }
    WAITG(2); __syncthreads();                              // c=60
    load_fast(stA[3], stB[3], pAd, pBd); CP_COMMIT();       // prefetch 63
    compute_chunk(cstg[0], aOff0, bOff0, acc);
    WAITG(2); __syncthreads();                              // c=61
    load_tail(stA[0], stB[0], m0, n0, bb, t); CP_COMMIT();  // prefetch 64 (LoRA)
    compute_chunk(cstg[1], aOff0, bOff0, acc);
    WAITG(2); __syncthreads();                              // c=62
    compute_chunk(cstg[2], aOff0, bOff0, acc);
    WAITG(1); __syncthreads();                              // c=63
    compute_chunk(cstg[3], aOff0, bOff0, acc);
    WAITG(0); __syncthreads();                              // c=64 (LoRA)
    compute_chunk(cstg[0], aOff0, bOff0, acc);

    #pragma unroll
    for (int mf = 0; mf < 4; mf++) {
        const int r0 = m0 + warpM * 64 + mf * 16 + gID;
        #pragma unroll
        for (int nf = 0; nf < 4; nf++) {
            const int col = warpN * 32 + nf * 8 + 2 * g;
            const float b0 = bias_s[col], b1 = bias_s[col + 1];
            float2 v0, v1;
            v0.x = acc[mf][nf][0] + b0; v0.y = acc[mf][nf][1] + b1;
            v1.x = acc[mf][nf][2] + b0; v1.y = acc[mf][nf][3] + b1;
            *reinterpret_cast<float2*>(out + (size_t)r0 * DO + n0 + col) = v0;
            *reinterpret_cast<float2*>(out + (size_t)(r0 + 8) * DO + n0 + col) = v1;
        }
    }
}

// ------------------------------- launch -------------------------------------
extern "C" void kernel_launch(void* const* d_in, const int* /*in_sizes*/, int /*n_in*/,
                              void* d_out, int /*out_size*/) {
    const float* x  = (const float*)d_in[0];
    const float* W  = (const float*)d_in[1];
    const float* b  = (const float*)d_in[2];
    const float* da = (const float*)d_in[3];
    const float* ua = (const float*)d_in[4];
    const float* hd = (const float*)d_in[5];
    const float* hu = (const float*)d_in[6];
    float* out = (float*)d_out;

    cudaFuncSetAttribute(gemm_kernel, cudaFuncAttributeMaxDynamicSharedMemorySize, SMEM_BYTES);

    prep_small_kernel<<<128, 256>>>(da, ua, hd, hu);        // launch 1
    wconv_kernel<<<DO * DI / 16 / 256, 256>>>(W);           // launch 2
    lowrank_kernel<<<MTOT / 16, 256>>>(x);                  // launch 3
    gemm_kernel<<<dim3(DO / TN, MTOT / TM), 512, SMEM_BYTES>>>(b, out);  // launch 4 (ncu)
}

// round 15
// speedup vs baseline: 1.1810x; 1.0150x over previous
#include <cuda_runtime.h>
#include <cuda_fp16.h>
#include <cstdint>
#include <cstddef>

constexpr int BATCH = 4, SEQ = 2048, DI = 4096, DO = 4096, RANK = 16;
constexpr int MTOT = BATCH * SEQ;          // 8192
constexpr float LORA_SCALE = 2.0f;         // ALPHA / RANK

constexpr int TM = 256, TN = 128, KC = 64; // K-chunk = 64 fp16 = 128B rows
constexpr int STAGES = 4;
constexpr int NCHUNK = DI / KC;            // 64 real chunks; chunk 64 = LoRA chunk
constexpr int A_BYTES = TM * 128;          // 32 KB
constexpr int B_BYTES = TN * 128;          // 16 KB
constexpr int STAGE_BYTES = A_BYTES + B_BYTES;           // 48 KB
constexpr int SMEM_BYTES = 1024 + STAGES * STAGE_BYTES;  // 197632

// Row swizzle over 16B chunk index (3 bits), conflict-free for v4 frag loads.
#define SWZ(r) (((((r) & 1) << 2) | (((r) >> 1) & 3)))

// ---------------- scratch (__device__ globals: allocation-free) -------------
__device__ __align__(128) __half g_xp[(size_t)MTOT * DI];
__device__ __align__(128) __half g_wp[(size_t)DO * DI];
__device__ __align__(128) __half g_downh[BATCH * RANK * DI];      // fp16, scale folded
__device__ __align__(128) __half g_upp[(size_t)BATCH * DO * 64];  // K padded 64, perm
__device__ __align__(128) __half g_lrp[(size_t)MTOT * 64];        // K padded 64, perm

#define DEVFN __device__ __forceinline__

DEVFN uint32_t s2u(const void* p) {
    uint32_t a;
    asm("{ .reg .u64 t; cvta.to.shared.u64 t, %1; cvt.u32.u64 %0, t; }" : "=r"(a) : "l"(p));
    return a;
}
DEVFN void cp_async16(uint32_t dst, const void* src) {
    unsigned long long g = (unsigned long long)__cvta_generic_to_global((void*)src);
    asm volatile("cp.async.cg.shared.global [%0], [%1], 16;" :: "r"(dst), "l"(g));
}
#define CP_COMMIT() asm volatile("cp.async.commit_group;" ::: "memory")

DEVFN uint4 lds_v4u(uint32_t addr) {
    uint4 v;
    asm volatile("ld.shared.v4.b32 {%0,%1,%2,%3}, [%4];"
                 : "=r"(v.x), "=r"(v.y), "=r"(v.z), "=r"(v.w) : "r"(addr));
    return v;
}

// fp32-accumulate HMMA
DEVFN void mma16(float* d, uint32_t a0, uint32_t a1, uint32_t a2, uint32_t a3,
                 uint32_t b0, uint32_t b1) {
    asm volatile("mma.sync.aligned.m16n8k16.row.col.f32.f16.f16.f32 "
                 "{%0,%1,%2,%3}, {%4,%5,%6,%7}, {%8,%9}, {%0,%1,%2,%3};"
                 : "+f"(d[0]), "+f"(d[1]), "+f"(d[2]), "+f"(d[3])
                 : "r"(a0), "r"(a1), "r"(a2), "r"(a3), "r"(b0), "r"(b1));
}

DEVFN uint32_t h2u(__half2 h) { return *reinterpret_cast<uint32_t*>(&h); }

// ------------------------- small factors prep kernel ------------------------
// blocks [0,64): down factors (fp16 out); [64,128): up factors
__global__ __launch_bounds__(256) void prep_small_kernel(
    const float* __restrict__ da, const float* __restrict__ ua,
    const float* __restrict__ hd, const float* __restrict__ hu)
{
    __shared__ float hs[1024];
    const int bid = blockIdx.x, t = threadIdx.x;
    if (bid < 64) {
        const int b = bid >> 4;
        const int i = (bid & 15) * 256 + t;
        for (int j = t; j < 1024; j += 256) hs[j] = hd[b * 1024 + j];  // hs[a*16+r]
        __syncthreads();
        float acc[16];
        #pragma unroll
        for (int r = 0; r < 16; r++) acc[r] = 0.f;
        const float4* dap = reinterpret_cast<const float4*>(da + (size_t)i * 64);
        #pragma unroll 4
        for (int aq = 0; aq < 16; aq++) {
            float4 v = dap[aq];
            #pragma unroll
            for (int r = 0; r < 16; r++)
                acc[r] += v.x * hs[(aq * 4 + 0) * 16 + r] + v.y * hs[(aq * 4 + 1) * 16 + r]
                        + v.z * hs[(aq * 4 + 2) * 16 + r] + v.w * hs[(aq * 4 + 3) * 16 + r];
        }
        #pragma unroll
        for (int r = 0; r < 16; r++)
            g_downh[((size_t)b * RANK + r) * DI + i] = __float2half(LORA_SCALE * acc[r]);
    } else {
        const int bb2 = bid - 64;
        const int b = bb2 >> 4;
        const int o = (bb2 & 15) * 256 + t;
        for (int j = t; j < 1024; j += 256) hs[j] = hu[b * 1024 + j];  // hs[c*64+a]
        __syncthreads();
        float acc[16];
        #pragma unroll
        for (int c = 0; c < 16; c++) acc[c] = 0.f;
        #pragma unroll 4
        for (int a = 0; a < 64; a++) {
            float uv = ua[(size_t)a * DO + o];
            #pragma unroll
            for (int c = 0; c < 16; c++) acc[c] += uv * hs[c * 64 + a];
        }
        __half* op = g_upp + ((size_t)b * DO + o) * 64;
        #pragma unroll
        for (int q = 0; q < 4; q++) {
            uint2 v;
            v.x = h2u(__floats2half2_rn(acc[2 * q], acc[2 * q + 1]));
            v.y = h2u(__floats2half2_rn(acc[2 * q + 8], acc[2 * q + 9]));
            *reinterpret_cast<uint2*>(op + q * 8) = v;
            *reinterpret_cast<uint2*>(op + q * 8 + 4) = make_uint2(0, 0);
        }
        #pragma unroll
        for (int q = 0; q < 4; q++)
            *reinterpret_cast<uint4*>(op + 32 + q * 8) = make_uint4(0, 0, 0, 0);
    }
}

// smem swizzle for down_s: XOR 16B-chunk index with (chunk>>3)&7
DEVFN int dswz(int kk) {
    int c = kk >> 2;
    return ((c ^ ((c >> 3) & 7)) << 2) | (kk & 3);
}

// -------------- merged lowrank + W convert kernel ---------------------------
// blocks [0,512): lowrank (16 rows each); [512, 512+4096): W convert.
// Independent work sets — wconv blocks fill SMs while lowrank blocks run.
__global__ __launch_bounds__(256) void lw_kernel(const float* __restrict__ x,
                                                 const float* __restrict__ W) {
    __shared__ float down_s[16 * 512];
    const int t = threadIdx.x;
    if (blockIdx.x >= 512) {
        // ---- W convert: one (s,G) half-supergroup (16 k) per thread ----
        const size_t tid = (size_t)(blockIdx.x - 512) * 256 + t;
        const size_t grp = tid >> 2;
        const int off = (int)(tid & 3) * 16;
        const int sb = ((off >> 5) & 1) * 32 + ((off >> 4) & 1) * 4;
        const float* wp = W + grp * 64 + off;
        float v[16];
        #pragma unroll
        for (int q = 0; q < 4; q++) {
            float4 f = reinterpret_cast<const float4*>(wp)[q];
            v[4 * q] = f.x; v[4 * q + 1] = f.y; v[4 * q + 2] = f.z; v[4 * q + 3] = f.w;
        }
        __half* op = g_wp + grp * 64 + sb;
        #pragma unroll
        for (int g4 = 0; g4 < 4; g4++) {
            uint2 u;
            u.x = h2u(__floats2half2_rn(v[2 * g4], v[2 * g4 + 1]));
            u.y = h2u(__floats2half2_rn(v[8 + 2 * g4], v[9 + 2 * g4]));
            *reinterpret_cast<uint2*>(op + g4 * 8) = u;
        }
        return;
    }
    // ---- lowrank: x -> fp16+perm copy AND low_rank = x @ down^T ----
    const int m0 = blockIdx.x * 16;
    const int bb = m0 / SEQ;
    const int w = t >> 5, l = t & 31;
    const int rowbase = m0 + w * 2;
    const __half* dwb = g_downh + (size_t)bb * RANK * DI;

    const int ks = l * 16;
    const int o0 = dswz(ks), o1 = dswz(ks + 4), o2 = dswz(ks + 8), o3 = dswz(ks + 12);

    float acc[2][16];
    #pragma unroll
    for (int j = 0; j < 2; j++)
        #pragma unroll
        for (int r = 0; r < 16; r++) acc[j][r] = 0.f;

    for (int k0 = 0; k0 < DI; k0 += 512) {
        __syncthreads();
        for (int j = t; j < 16 * 512 / 2; j += 256) {
            int r = j >> 8, kk2 = (j & 255) * 2;
            __half2 hv = *reinterpret_cast<const __half2*>(dwb + r * DI + k0 + kk2);
            float2 fv = __half22float2(hv);
            down_s[r * 512 + dswz(kk2)] = fv.x;
            down_s[r * 512 + dswz(kk2 + 1)] = fv.y;
        }
        __syncthreads();
        const int gk = k0 + ks;
        const int grp = gk & ~63, off = gk & 63;
        const int sb = ((off >> 5) & 1) * 32 + ((off >> 4) & 1) * 4;
        float v[2][16];
        #pragma unroll
        for (int j = 0; j < 2; j++) {
            const float* xr = x + (size_t)(rowbase + j) * DI + gk;
            #pragma unroll
            for (int q = 0; q < 4; q++) {
                float4 f = reinterpret_cast<const float4*>(xr)[q];
                v[j][4 * q] = f.x; v[j][4 * q + 1] = f.y;
                v[j][4 * q + 2] = f.z; v[j][4 * q + 3] = f.w;
            }
            __half* op = g_xp + (size_t)(rowbase + j) * DI + grp + sb;
            #pragma unroll
            for (int g4 = 0; g4 < 4; g4++) {
                uint2 u;
                u.x = h2u(__floats2half2_rn(v[j][2 * g4], v[j][2 * g4 + 1]));
                u.y = h2u(__floats2half2_rn(v[j][8 + 2 * g4], v[j][9 + 2 * g4]));
                *reinterpret_cast<uint2*>(op + g4 * 8) = u;
            }
        }
        // down_s fragments loaded ONCE per rank, reused for both rows
        #pragma unroll
        for (int r = 0; r < 16; r++) {
            const float* dr = down_s + r * 512;
            float4 d0 = *reinterpret_cast<const float4*>(dr + o0);
            float4 d1 = *reinterpret_cast<const float4*>(dr + o1);
            float4 d2 = *reinterpret_cast<const float4*>(dr + o2);
            float4 d3 = *reinterpret_cast<const float4*>(dr + o3);
            #pragma unroll
            for (int j = 0; j < 2; j++) {
                acc[j][r] += v[j][0] * d0.x + v[j][1] * d0.y + v[j][2] * d0.z + v[j][3] * d0.w
                           + v[j][4] * d1.x + v[j][5] * d1.y + v[j][6] * d1.z + v[j][7] * d1.w
                           + v[j][8] * d2.x + v[j][9] * d2.y + v[j][10] * d2.z + v[j][11] * d2.w
                           + v[j][12] * d3.x + v[j][13] * d3.y + v[j][14] * d3.z + v[j][15] * d3.w;
            }
        }
    }
    #pragma unroll
    for (int j = 0; j < 2; j++) {
        #pragma unroll
        for (int r = 0; r < 16; r++) {
            float vv = acc[j][r];
            vv += __shfl_xor_sync(~0u, vv, 16);
            vv += __shfl_xor_sync(~0u, vv, 8);
            vv += __shfl_xor_sync(~0u, vv, 4);
            vv += __shfl_xor_sync(~0u, vv, 2);
            vv += __shfl_xor_sync(~0u, vv, 1);
            acc[j][r] = vv;
        }
        if (l == 0) {
            __half* op = g_lrp + (size_t)(rowbase + j) * 64;
            #pragma unroll
            for (int q = 0; q < 4; q++) {
                uint2 u;
                u.x = h2u(__floats2half2_rn(acc[j][2 * q], acc[j][2 * q + 1]));
                u.y = h2u(__floats2half2_rn(acc[j][2 * q + 8], acc[j][2 * q + 9]));
                *reinterpret_cast<uint2*>(op + q * 8) = u;
                *reinterpret_cast<uint2*>(op + q * 8 + 4) = make_uint2(0, 0);
            }
            #pragma unroll
            for (int q = 0; q < 4; q++)
                *reinterpret_cast<uint4*>(op + 32 + q * 8) = make_uint4(0, 0, 0, 0);
        }
    }
}

// ------------------------------- main GEMM ----------------------------------
// 512 threads, 16 warps (4x4), warp tile 64x32, fp16 m16n8k16, 4 stages.
DEVFN void load_fast(uint32_t sdstA, uint32_t sdstB,
                     const __half* pA, const __half* pB) {
    #pragma unroll
    for (int q = 0; q < 4; q++)
        cp_async16(sdstA + q * 8192, pA + (size_t)q * 64 * DI);
    #pragma unroll
    for (int q = 0; q < 2; q++)
        cp_async16(sdstB + q * 8192, pB + (size_t)q * 64 * DI);
}

DEVFN void load_tail(uint32_t sdstA, uint32_t sdstB, int m0, int n0, int bb, int t) {
    const int ro = (t >> 3) * 64 + (t & 7) * 8;
    const __half* ap = g_lrp + (size_t)m0 * 64 + ro;
    const __half* bp = g_upp + ((size_t)bb * DO + n0) * 64 + ro;
    #pragma unroll
    for (int q = 0; q < 4; q++)
        cp_async16(sdstA + q * 8192, ap + q * 64 * 64);
    #pragma unroll
    for (int q = 0; q < 2; q++)
        cp_async16(sdstB + q * 8192, bp + q * 64 * 64);
}

DEVFN void compute_chunk(uint32_t sbase, uint32_t aOff0, uint32_t bOff0,
                         float acc[4][4][4]) {
    #pragma unroll
    for (int s = 0; s < 2; s++) {
        const uint32_t aB = sbase + (s ? (aOff0 ^ 64u) : aOff0);
        const uint32_t bB = sbase + (s ? (bOff0 ^ 64u) : bOff0);
        uint4 Bf[4];
        #pragma unroll
        for (int j = 0; j < 4; j++)
            Bf[j] = lds_v4u(bB + j * 1024);
        #pragma unroll
        for (int mf = 0; mf < 4; mf++) {
            uint4 A0 = lds_v4u(aB + mf * 2048);
            uint4 A1 = lds_v4u(aB + mf * 2048 + 1024);
            #pragma unroll
            for (int j = 0; j < 4; j++) {
                float* d = acc[mf][j];
                mma16(d, A0.x, A1.x, A0.y, A1.y, Bf[j].x, Bf[j].y);
                mma16(d, A0.z, A1.z, A0.w, A1.w, Bf[j].z, Bf[j].w);
            }
        }
    }
}

#define WAITG(n) asm volatile("cp.async.wait_group " #n ";" ::: "memory")

__global__ void __launch_bounds__(512, 1)
gemm_kernel(const float* __restrict__ bias, float* __restrict__ out) {
    extern __shared__ char smem_raw[];
    float* bias_s = reinterpret_cast<float*>(smem_raw);   // 128 floats
    const uint32_t stage_u = s2u(smem_raw + 1024);

    const int t = threadIdx.x;
    const int wid = t >> 5, lane = t & 31;
    const int gID = lane >> 2, g = lane & 3;
    const int warpM = wid >> 2, warpN = wid & 3;          // 4 x 4 warps, 64x32 tiles

    const int n0 = blockIdx.x * TN;
    const int m0 = blockIdx.y * TM;
    const int bb = m0 / SEQ;

    if (t < TN) bias_s[t] = bias[n0 + t];

    const uint32_t swzg = (uint32_t)((g ^ SWZ(gID)) << 4);
    const uint32_t aOff0 = (uint32_t)(warpM * 8192 + gID * 128) + swzg;
    const uint32_t bOff0 = (uint32_t)A_BYTES + (uint32_t)(warpN * 4096 + gID * 128) + swzg;

    const uint32_t dSwz = (uint32_t)((t >> 3) * 128)
                        + (uint32_t)((((t & 7) ^ SWZ((t >> 3) & 7))) << 4);
    uint32_t stA[4], stB[4], cstg[4];
    #pragma unroll
    for (int s = 0; s < 4; s++) {
        cstg[s] = stage_u + s * STAGE_BYTES;
        stA[s] = cstg[s] + dSwz;
        stB[s] = stA[s] + A_BYTES;
    }

    const int gro = (t >> 3) * DI + (t & 7) * 8;
    const __half* pA0 = g_xp + (size_t)m0 * DI + gro;
    const __half* pB0 = g_wp + (size_t)n0 * DI + gro;

    float acc[4][4][4];
    #pragma unroll
    for (int mf = 0; mf < 4; mf++)
        #pragma unroll
        for (int nf = 0; nf < 4; nf++)
            #pragma unroll
            for (int k = 0; k < 4; k++) acc[mf][nf][k] = 0.f;

    load_fast(stA[0], stB[0], pA0, pB0);                   CP_COMMIT();
    load_fast(stA[1], stB[1], pA0 + KC, pB0 + KC);         CP_COMMIT();
    load_fast(stA[2], stB[2], pA0 + 2 * KC, pB0 + 2 * KC); CP_COMMIT();
    const __half* pAd = pA0 + 3 * KC;
    const __half* pBd = pB0 + 3 * KC;

    for (int c4 = 0; c4 < 60; c4 += 4) {
        #pragma unroll
        for (int u = 0; u < 4; u++) {
            WAITG(2);
            __syncthreads();
            load_fast(stA[(u + 3) & 3], stB[(u + 3) & 3], pAd, pBd);
            CP_COMMIT();
            pAd += KC; pBd += KC;
            compute_chunk(cstg[u], aOff0, bOff0, acc);
        }
    }
    WAITG(2); __syncthreads();                              // c=60
    load_fast(stA[3], stB[3], pAd, pBd); CP_COMMIT();       // prefetch 63
    compute_chunk(cstg[0], aOff0, bOff0, acc);
    WAITG(2); __syncthreads();                              // c=61
    load_tail(stA[0], stB[0], m0, n0, bb, t); CP_COMMIT();  // prefetch 64 (LoRA)
    compute_chunk(cstg[1], aOff0, bOff0, acc);
    WAITG(2); __syncthreads();                              // c=62
    compute_chunk(cstg[2], aOff0, bOff0, acc);
    WAITG(1); __syncthreads();                              // c=63
    compute_chunk(cstg[3], aOff0, bOff0, acc);
    WAITG(0); __syncthreads();                              // c=64 (LoRA)
    compute_chunk(cstg[0], aOff0, bOff0, acc);

    #pragma unroll
    for (int mf = 0; mf < 4; mf++) {
        const int r0 = m0 + warpM * 64 + mf * 16 + gID;
        #pragma unroll
        for (int nf = 0; nf < 4; nf++) {
            const int col = warpN * 32 + nf * 8 + 2 * g;
            const float b0 = bias_s[col], b1 = bias_s[col + 1];
            float2 v0, v1;
            v0.x = acc[mf][nf][0] + b0; v0.y = acc[mf][nf][1] + b1;
            v1.x = acc[mf][nf][2] + b0; v1.y = acc[mf][nf][3] + b1;
            *reinterpret_cast<float2*>(out + (size_t)r0 * DO + n0 + col) = v0;
            *reinterpret_cast<float2*>(out + (size_t)(r0 + 8) * DO + n0 + col) = v1;
        }
    }
}

// ------------------------------- launch -------------------------------------
extern "C" void kernel_launch(void* const* d_in, const int* /*in_sizes*/, int /*n_in*/,
                              void* d_out, int /*out_size*/) {
    const float* x  = (const float*)d_in[0];
    const float* W  = (const float*)d_in[1];
    const float* b  = (const float*)d_in[2];
    const float* da = (const float*)d_in[3];
    const float* ua = (const float*)d_in[4];
    const float* hd = (const float*)d_in[5];
    const float* hu = (const float*)d_in[6];
    float* out = (float*)d_out;

    cudaFuncSetAttribute(gemm_kernel, cudaFuncAttributeMaxDynamicSharedMemorySize, SMEM_BYTES);

    prep_small_kernel<<<128, 256>>>(da, ua, hd, hu);
    lw_kernel<<<512 + DO * DI / 16 / 256, 256>>>(x, W);
    gemm_kernel<<<dim3(DO / TN, MTOT / TM), 512, SMEM_BYTES>>>(b, out);
}

// round 16
// speedup vs baseline: 1.1820x; 1.0009x over previous
#include <cuda_runtime.h>
#include <cuda_fp16.h>
#include <cstdint>
#include <cstddef>

constexpr int BATCH = 4, SEQ = 2048, DI = 4096, DO = 4096, RANK = 16;
constexpr int MTOT = BATCH * SEQ;          // 8192
constexpr float LORA_SCALE = 2.0f;         // ALPHA / RANK

constexpr int TM = 256, TN = 128, KC = 64; // K-chunk = 64 fp16 = 128B rows
constexpr int STAGES = 4;
constexpr int NCHUNK = DI / KC;            // 64 real chunks; chunk 64 = LoRA chunk
constexpr int A_BYTES = TM * 128;          // 32 KB
constexpr int B_BYTES = TN * 128;          // 16 KB
constexpr int STAGE_BYTES = A_BYTES + B_BYTES;           // 48 KB
constexpr int SMEM_BYTES = 1024 + STAGES * STAGE_BYTES;  // 197632

// Row swizzle over 16B chunk index (3 bits), conflict-free for v4 frag loads.
#define SWZ(r) (((((r) & 1) << 2) | (((r) >> 1) & 3)))

// ---------------- scratch (__device__ globals: allocation-free) -------------
__device__ __align__(128) __half g_xp[(size_t)MTOT * DI];
__device__ __align__(128) __half g_wp[(size_t)DO * DI];
__device__ __align__(128) __half g_downh[BATCH * RANK * DI];      // fp16, scale folded
__device__ __align__(128) __half g_upp[(size_t)BATCH * DO * 64];  // K padded 64, perm
__device__ __align__(128) __half g_lrp[(size_t)MTOT * 64];        // K padded 64, perm

#define DEVFN __device__ __forceinline__

DEVFN uint32_t s2u(const void* p) {
    uint32_t a;
    asm("{ .reg .u64 t; cvta.to.shared.u64 t, %1; cvt.u32.u64 %0, t; }" : "=r"(a) : "l"(p));
    return a;
}
DEVFN void cp_async16(uint32_t dst, const void* src) {
    unsigned long long g = (unsigned long long)__cvta_generic_to_global((void*)src);
    asm volatile("cp.async.cg.shared.global [%0], [%1], 16;" :: "r"(dst), "l"(g));
}
#define CP_COMMIT() asm volatile("cp.async.commit_group;" ::: "memory")

DEVFN uint4 lds_v4u(uint32_t addr) {
    uint4 v;
    asm volatile("ld.shared.v4.b32 {%0,%1,%2,%3}, [%4];"
                 : "=r"(v.x), "=r"(v.y), "=r"(v.z), "=r"(v.w) : "r"(addr));
    return v;
}

// fp32-accumulate HMMA
DEVFN void mma16(float* d, uint32_t a0, uint32_t a1, uint32_t a2, uint32_t a3,
                 uint32_t b0, uint32_t b1) {
    asm volatile("mma.sync.aligned.m16n8k16.row.col.f32.f16.f16.f32 "
                 "{%0,%1,%2,%3}, {%4,%5,%6,%7}, {%8,%9}, {%0,%1,%2,%3};"
                 : "+f"(d[0]), "+f"(d[1]), "+f"(d[2]), "+f"(d[3])
                 : "r"(a0), "r"(a1), "r"(a2), "r"(a3), "r"(b0), "r"(b1));
}

DEVFN uint32_t h2u(__half2 h) { return *reinterpret_cast<uint32_t*>(&h); }

// ------------------------- small factors prep kernel (4x parallel) ----------
// blocks [0,256): down factors; [256,512): up factors.
// 4 threads per output, each covering a 16-wide quarter of the a-reduction;
// combined with 2 shfl_xor steps (adjacent lanes form the group of 4).
__global__ __launch_bounds__(256) void prep_small_kernel(
    const float* __restrict__ da, const float* __restrict__ ua,
    const float* __restrict__ hd, const float* __restrict__ hu)
{
    __shared__ float hs[1024];
    const int bid = blockIdx.x, t = threadIdx.x;
    const int aq = t & 3;                 // quarter index within output group
    if (bid < 256) {
        // down[b][r][i] = scale * sum_a da[i,a] * hd[b,a,r]
        const int b = bid >> 6;
        const int i = ((bid & 63) << 6) + (t >> 2);     // 64 outputs per block
        for (int j = t; j < 1024; j += 256) hs[j] = hd[b * 1024 + j];  // hs[a*16+r]
        __syncthreads();
        float acc[16];
        #pragma unroll
        for (int r = 0; r < 16; r++) acc[r] = 0.f;
        const float4* dap = reinterpret_cast<const float4*>(da + (size_t)i * 64 + aq * 16);
        #pragma unroll
        for (int q4 = 0; q4 < 4; q4++) {
            float4 v = dap[q4];
            const int a0 = aq * 16 + q4 * 4;
            #pragma unroll
            for (int r = 0; r < 16; r++)
                acc[r] += v.x * hs[(a0 + 0) * 16 + r] + v.y * hs[(a0 + 1) * 16 + r]
                        + v.z * hs[(a0 + 2) * 16 + r] + v.w * hs[(a0 + 3) * 16 + r];
        }
        #pragma unroll
        for (int r = 0; r < 16; r++) {
            acc[r] += __shfl_xor_sync(~0u, acc[r], 1);
            acc[r] += __shfl_xor_sync(~0u, acc[r], 2);
        }
        if (aq == 0) {
            #pragma unroll
            for (int r = 0; r < 16; r++)
                g_downh[((size_t)b * RANK + r) * DI + i] = __float2half(LORA_SCALE * acc[r]);
        }
    } else {
        // up[b][o][c] = sum_a ua[a,o] * hu[b,c,a]; store fp16 permuted+padded
        const int bb2 = bid - 256;
        const int b = bb2 >> 6;
        const int o = ((bb2 & 63) << 6) + (t >> 2);
        for (int j = t; j < 1024; j += 256) hs[j] = hu[b * 1024 + j];  // hs[c*64+a]
        __syncthreads();
        float acc[16];
        #pragma unroll
        for (int c = 0; c < 16; c++) acc[c] = 0.f;
        #pragma unroll
        for (int ai = 0; ai < 16; ai++) {
            const int a = aq * 16 + ai;
            float uv = ua[(size_t)a * DO + o];
            #pragma unroll
            for (int c = 0; c < 16; c++) acc[c] += uv * hs[c * 64 + a];
        }
        #pragma unroll
        for (int c = 0; c < 16; c++) {
            acc[c] += __shfl_xor_sync(~0u, acc[c], 1);
            acc[c] += __shfl_xor_sync(~0u, acc[c], 2);
        }
        if (aq == 0) {
            __half* op = g_upp + ((size_t)b * DO + o) * 64;
            #pragma unroll
            for (int q = 0; q < 4; q++) {
                uint2 v;
                v.x = h2u(__floats2half2_rn(acc[2 * q], acc[2 * q + 1]));
                v.y = h2u(__floats2half2_rn(acc[2 * q + 8], acc[2 * q + 9]));
                *reinterpret_cast<uint2*>(op + q * 8) = v;
                *reinterpret_cast<uint2*>(op + q * 8 + 4) = make_uint2(0, 0);
            }
            #pragma unroll
            for (int q = 0; q < 4; q++)
                *reinterpret_cast<uint4*>(op + 32 + q * 8) = make_uint4(0, 0, 0, 0);
        }
    }
}

// smem swizzle for down_s: XOR 16B-chunk index with (chunk>>3)&7
DEVFN int dswz(int kk) {
    int c = kk >> 2;
    return ((c ^ ((c >> 3) & 7)) << 2) | (kk & 3);
}

// -------------- merged lowrank + W convert kernel ---------------------------
// blocks [0,512): lowrank (16 rows each); [512, 512+4096): W convert.
__global__ __launch_bounds__(256) void lw_kernel(const float* __restrict__ x,
                                                 const float* __restrict__ W) {
    __shared__ float down_s[16 * 512];
    const int t = threadIdx.x;
    if (blockIdx.x >= 512) {
        // ---- W convert: one (s,G) half-supergroup (16 k) per thread ----
        const size_t tid = (size_t)(blockIdx.x - 512) * 256 + t;
        const size_t grp = tid >> 2;
        const int off = (int)(tid & 3) * 16;
        const int sb = ((off >> 5) & 1) * 32 + ((off >> 4) & 1) * 4;
        const float* wp = W + grp * 64 + off;
        float v[16];
        #pragma unroll
        for (int q = 0; q < 4; q++) {
            float4 f = reinterpret_cast<const float4*>(wp)[q];
            v[4 * q] = f.x; v[4 * q + 1] = f.y; v[4 * q + 2] = f.z; v[4 * q + 3] = f.w;
        }
        __half* op = g_wp + grp * 64 + sb;
        #pragma unroll
        for (int g4 = 0; g4 < 4; g4++) {
            uint2 u;
            u.x = h2u(__floats2half2_rn(v[2 * g4], v[2 * g4 + 1]));
            u.y = h2u(__floats2half2_rn(v[8 + 2 * g4], v[9 + 2 * g4]));
            *reinterpret_cast<uint2*>(op + g4 * 8) = u;
        }
        return;
    }
    // ---- lowrank: x -> fp16+perm copy AND low_rank = x @ down^T ----
    const int m0 = blockIdx.x * 16;
    const int bb = m0 / SEQ;
    const int w = t >> 5, l = t & 31;
    const int rowbase = m0 + w * 2;
    const __half* dwb = g_downh + (size_t)bb * RANK * DI;

    const int ks = l * 16;
    const int o0 = dswz(ks), o1 = dswz(ks + 4), o2 = dswz(ks + 8), o3 = dswz(ks + 12);

    float acc[2][16];
    #pragma unroll
    for (int j = 0; j < 2; j++)
        #pragma unroll
        for (int r = 0; r < 16; r++) acc[j][r] = 0.f;

    for (int k0 = 0; k0 < DI; k0 += 512) {
        __syncthreads();
        for (int j = t; j < 16 * 512 / 2; j += 256) {
            int r = j >> 8, kk2 = (j & 255) * 2;
            __half2 hv = *reinterpret_cast<const __half2*>(dwb + r * DI + k0 + kk2);
            float2 fv = __half22float2(hv);
            down_s[r * 512 + dswz(kk2)] = fv.x;
            down_s[r * 512 + dswz(kk2 + 1)] = fv.y;
        }
        __syncthreads();
        const int gk = k0 + ks;
        const int grp = gk & ~63, off = gk & 63;
        const int sb = ((off >> 5) & 1) * 32 + ((off >> 4) & 1) * 4;
        float v[2][16];
        #pragma unroll
        for (int j = 0; j < 2; j++) {
            const float* xr = x + (size_t)(rowbase + j) * DI + gk;
            #pragma unroll
            for (int q = 0; q < 4; q++) {
                float4 f = reinterpret_cast<const float4*>(xr)[q];
                v[j][4 * q] = f.x; v[j][4 * q + 1] = f.y;
                v[j][4 * q + 2] = f.z; v[j][4 * q + 3] = f.w;
            }
            __half* op = g_xp + (size_t)(rowbase + j) * DI + grp + sb;
            #pragma unroll
            for (int g4 = 0; g4 < 4; g4++) {
                uint2 u;
                u.x = h2u(__floats2half2_rn(v[j][2 * g4], v[j][2 * g4 + 1]));
                u.y = h2u(__floats2half2_rn(v[j][8 + 2 * g4], v[j][9 + 2 * g4]));
                *reinterpret_cast<uint2*>(op + g4 * 8) = u;
            }
        }
        #pragma unroll
        for (int r = 0; r < 16; r++) {
            const float* dr = down_s + r * 512;
            float4 d0 = *reinterpret_cast<const float4*>(dr + o0);
            float4 d1 = *reinterpret_cast<const float4*>(dr + o1);
            float4 d2 = *reinterpret_cast<const float4*>(dr + o2);
            float4 d3 = *reinterpret_cast<const float4*>(dr + o3);
            #pragma unroll
            for (int j = 0; j < 2; j++) {
                acc[j][r] += v[j][0] * d0.x + v[j][1] * d0.y + v[j][2] * d0.z + v[j][3] * d0.w
                           + v[j][4] * d1.x + v[j][5] * d1.y + v[j][6] * d1.z + v[j][7] * d1.w
                           + v[j][8] * d2.x + v[j][9] * d2.y + v[j][10] * d2.z + v[j][11] * d2.w
                           + v[j][12] * d3.x + v[j][13] * d3.y + v[j][14] * d3.z + v[j][15] * d3.w;
            }
        }
    }
    #pragma unroll
    for (int j = 0; j < 2; j++) {
        #pragma unroll
        for (int r = 0; r < 16; r++) {
            float vv = acc[j][r];
            vv += __shfl_xor_sync(~0u, vv, 16);
            vv += __shfl_xor_sync(~0u, vv, 8);
            vv += __shfl_xor_sync(~0u, vv, 4);
            vv += __shfl_xor_sync(~0u, vv, 2);
            vv += __shfl_xor_sync(~0u, vv, 1);
            acc[j][r] = vv;
        }
        if (l == 0) {
            __half* op = g_lrp + (size_t)(rowbase + j) * 64;
            #pragma unroll
            for (int q = 0; q < 4; q++) {
                uint2 u;
                u.x = h2u(__floats2half2_rn(acc[j][2 * q], acc[j][2 * q + 1]));
                u.y = h2u(__floats2half2_rn(acc[j][2 * q + 8], acc[j][2 * q + 9]));
                *reinterpret_cast<uint2*>(op + q * 8) = u;
                *reinterpret_cast<uint2*>(op + q * 8 + 4) = make_uint2(0, 0);
            }
            #pragma unroll
            for (int q = 0; q < 4; q++)
                *reinterpret_cast<uint4*>(op + 32 + q * 8) = make_uint4(0, 0, 0, 0);
        }
    }
}

// ------------------------------- main GEMM ----------------------------------
// 512 threads, 16 warps (4x4), warp tile 64x32, fp16 m16n8k16, 4 stages.
DEVFN void load_fast(uint32_t sdstA, uint32_t sdstB,
                     const __half* pA, const __half* pB) {
    #pragma unroll
    for (int q = 0; q < 4; q++)
        cp_async16(sdstA + q * 8192, pA + (size_t)q * 64 * DI);
    #pragma unroll
    for (int q = 0; q < 2; q++)
        cp_async16(sdstB + q * 8192, pB + (size_t)q * 64 * DI);
}

DEVFN void load_tail(uint32_t sdstA, uint32_t sdstB, int m0, int n0, int bb, int t) {
    const int ro = (t >> 3) * 64 + (t & 7) * 8;
    const __half* ap = g_lrp + (size_t)m0 * 64 + ro;
    const __half* bp = g_upp + ((size_t)bb * DO + n0) * 64 + ro;
    #pragma unroll
    for (int q = 0; q < 4; q++)
        cp_async16(sdstA + q * 8192, ap + q * 64 * 64);
    #pragma unroll
    for (int q = 0; q < 2; q++)
        cp_async16(sdstB + q * 8192, bp + q * 64 * 64);
}

DEVFN void compute_chunk(uint32_t sbase, uint32_t aOff0, uint32_t bOff0,
                         float acc[4][4][4]) {
    #pragma unroll
    for (int s = 0; s < 2; s++) {
        const uint32_t aB = sbase + (s ? (aOff0 ^ 64u) : aOff0);
        const uint32_t bB = sbase + (s ? (bOff0 ^ 64u) : bOff0);
        uint4 Bf[4];
        #pragma unroll
        for (int j = 0; j < 4; j++)
            Bf[j] = lds_v4u(bB + j * 1024);
        #pragma unroll
        for (int mf = 0; mf < 4; mf++) {
            uint4 A0 = lds_v4u(aB + mf * 2048);
            uint4 A1 = lds_v4u(aB + mf * 2048 + 1024);
            #pragma unroll
            for (int j = 0; j < 4; j++) {
                float* d = acc[mf][j];
                mma16(d, A0.x, A1.x, A0.y, A1.y, Bf[j].x, Bf[j].y);
                mma16(d, A0.z, A1.z, A0.w, A1.w, Bf[j].z, Bf[j].w);
            }
        }
    }
}

#define WAITG(n) asm volatile("cp.async.wait_group " #n ";" ::: "memory")

__global__ void __launch_bounds__(512, 1)
gemm_kernel(const float* __restrict__ bias, float* __restrict__ out) {
    extern __shared__ char smem_raw[];
    float* bias_s = reinterpret_cast<float*>(smem_raw);   // 128 floats
    const uint32_t stage_u = s2u(smem_raw + 1024);

    const int t = threadIdx.x;
    const int wid = t >> 5, lane = t & 31;
    const int gID = lane >> 2, g = lane & 3;
    const int warpM = wid >> 2, warpN = wid & 3;          // 4 x 4 warps, 64x32 tiles

    const int n0 = blockIdx.x * TN;
    const int m0 = blockIdx.y * TM;
    const int bb = m0 / SEQ;

    if (t < TN) bias_s[t] = bias[n0 + t];

    const uint32_t swzg = (uint32_t)((g ^ SWZ(gID)) << 4);
    const uint32_t aOff0 = (uint32_t)(warpM * 8192 + gID * 128) + swzg;
    const uint32_t bOff0 = (uint32_t)A_BYTES + (uint32_t)(warpN * 4096 + gID * 128) + swzg;

    const uint32_t dSwz = (uint32_t)((t >> 3) * 128)
                        + (uint32_t)((((t & 7) ^ SWZ((t >> 3) & 7))) << 4);
    uint32_t stA[4], stB[4], cstg[4];
    #pragma unroll
    for (int s = 0; s < 4; s++) {
        cstg[s] = stage_u + s * STAGE_BYTES;
        stA[s] = cstg[s] + dSwz;
        stB[s] = stA[s] + A_BYTES;
    }

    const int gro = (t >> 3) * DI + (t & 7) * 8;
    const __half* pA0 = g_xp + (size_t)m0 * DI + gro;
    const __half* pB0 = g_wp + (size_t)n0 * DI + gro;

    float acc[4][4][4];
    #pragma unroll
    for (int mf = 0; mf < 4; mf++)
        #pragma unroll
        for (int nf = 0; nf < 4; nf++)
            #pragma unroll
            for (int k = 0; k < 4; k++) acc[mf][nf][k] = 0.f;

    load_fast(stA[0], stB[0], pA0, pB0);                   CP_COMMIT();
    load_fast(stA[1], stB[1], pA0 + KC, pB0 + KC);         CP_COMMIT();
    load_fast(stA[2], stB[2], pA0 + 2 * KC, pB0 + 2 * KC); CP_COMMIT();
    const __half* pAd = pA0 + 3 * KC;
    const __half* pBd = pB0 + 3 * KC;

    for (int c4 = 0; c4 < 60; c4 += 4) {
        #pragma unroll
        for (int u = 0; u < 4; u++) {
            WAITG(2);
            __syncthreads();
            load_fast(stA[(u + 3) & 3], stB[(u + 3) & 3], pAd, pBd);
            CP_COMMIT();
            pAd += KC; pBd += KC;
            compute_chunk(cstg[u], aOff0, bOff0, acc);
        }
    }
    WAITG(2); __syncthreads();                              // c=60
    load_fast(stA[3], stB[3], pAd, pBd); CP_COMMIT();       // prefetch 63
    compute_chunk(cstg[0], aOff0, bOff0, acc);
    WAITG(2); __syncthreads();                              // c=61
    load_tail(stA[0], stB[0], m0, n0, bb, t); CP_COMMIT();  // prefetch 64 (LoRA)
    compute_chunk(cstg[1], aOff0, bOff0, acc);
    WAITG(2); __syncthreads();                              // c=62
    compute_chunk(cstg[2], aOff0, bOff0, acc);
    WAITG(1); __syncthreads();                              // c=63
    compute_chunk(cstg[3], aOff0, bOff0, acc);
    WAITG(0); __syncthreads();                              // c=64 (LoRA)
    compute_chunk(cstg[0], aOff0, bOff0, acc);

    #pragma unroll
    for (int mf = 0; mf < 4; mf++) {
        const int r0 = m0 + warpM * 64 + mf * 16 + gID;
        #pragma unroll
        for (int nf = 0; nf < 4; nf++) {
            const int col = warpN * 32 + nf * 8 + 2 * g;
            const float b0 = bias_s[col], b1 = bias_s[col + 1];
            float2 v0, v1;
            v0.x = acc[mf][nf][0] + b0; v0.y = acc[mf][nf][1] + b1;
            v1.x = acc[mf][nf][2] + b0; v1.y = acc[mf][nf][3] + b1;
            *reinterpret_cast<float2*>(out + (size_t)r0 * DO + n0 + col) = v0;
            *reinterpret_cast<float2*>(out + (size_t)(r0 + 8) * DO + n0 + col) = v1;
        }
    }
}

// ------------------------------- launch -------------------------------------
extern "C" void kernel_launch(void* const* d_in, const int* /*in_sizes*/, int /*n_in*/,
                              void* d_out, int /*out_size*/) {
    const float* x  = (const float*)d_in[0];
    const float* W  = (const float*)d_in[1];
    const float* b  = (const float*)d_in[2];
    const float* da = (const float*)d_in[3];
    const float* ua = (const float*)d_in[4];
    const float* hd = (const float*)d_in[5];
    const float* hu = (const float*)d_in[6];
    float* out = (float*)d_out;

    cudaFuncSetAttribute(gemm_kernel, cudaFuncAttributeMaxDynamicSharedMemorySize, SMEM_BYTES);

    prep_small_kernel<<<512, 256>>>(da, ua, hd, hu);
    lw_kernel<<<512 + DO * DI / 16 / 256, 256>>>(x, W);
    gemm_kernel<<<dim3(DO / TN, MTOT / TM), 512, SMEM_BYTES>>>(b, out);
}